// round 4
// baseline (speedup 1.0000x reference)
#include <cuda_runtime.h>
#include <cstdint>

// Problem constants
#define B_    4
#define S_    2048
#define D_    1024
#define H_    16
#define DK_   64
#define DFF_  4096
#define M_    (B_*S_)   // 8192 rows
#define D3_   (3*D_)    // 3072

// ---------------------------------------------------------------------------
// Static device scratch (allocation-free rule)
// ---------------------------------------------------------------------------
__device__ float g_xn[M_*D_];               // LN1 output (permuted cols)
__device__ float g_qkv[M_*D3_];             // fused QKV output (permuted cols)
__device__ float g_ao[M_*D_];               // attention output (permuted cols)
__device__ float g_h [M_*D_];               // residual 1 (natural)
__device__ float g_hn[M_*D_];               // LN2 output (permuted)
__device__ float g_f1[M_*DFF_];             // FFN hidden (permuted)
__device__ float g_wqkv[D3_*D_];            // permuted concat weights
__device__ float g_wo[D_*D_];
__device__ float g_w1[DFF_*D_];
__device__ float g_w2[D_*DFF_];
__device__ float g_bqkv[D3_];

// ---------------------------------------------------------------------------
// Helpers
// ---------------------------------------------------------------------------
__device__ __forceinline__ float warpRedSum(float v){
    #pragma unroll
    for (int o=16;o;o>>=1) v += __shfl_xor_sync(0xffffffffu, v, o);
    return v;
}

__device__ __forceinline__ void mma8(float c[4], const uint32_t a[4], const uint32_t b[2]){
    asm volatile(
        "mma.sync.aligned.m16n8k8.row.col.f32.tf32.tf32.f32 "
        "{%0,%1,%2,%3}, {%4,%5,%6,%7}, {%8,%9}, {%0,%1,%2,%3};\n"
        : "+f"(c[0]), "+f"(c[1]), "+f"(c[2]), "+f"(c[3])
        : "r"(a[0]), "r"(a[1]), "r"(a[2]), "r"(a[3]),
          "r"(b[0]), "r"(b[1]));
}

__device__ __forceinline__ void cpa16(uint32_t dst, const void* src){
    asm volatile("cp.async.cg.shared.global [%0], [%1], 16;\n" :: "r"(dst), "l"(src));
}
__device__ __forceinline__ void cpcommit(){ asm volatile("cp.async.commit_group;\n"); }
__device__ __forceinline__ void cpwait1(){ asm volatile("cp.async.wait_group 1;\n"); }
__device__ __forceinline__ void cpwait0(){ asm volatile("cp.async.wait_group 0;\n"); }

// fragment-order permutation within 32-element K blocks: k -> (k%4)*8 + k/4
__device__ __forceinline__ int permc(int col){
    return (col & ~31) + ((col & 3) << 3) + ((col & 31) >> 2);
}
__device__ __forceinline__ float fc(const float4& v, int i){
    return i==0 ? v.x : i==1 ? v.y : i==2 ? v.z : v.w;
}

// ---------------------------------------------------------------------------
// Weight permute: dst[row][perm(col)] = src[row][col]
// ---------------------------------------------------------------------------
__global__ void wperm_kernel(const float* __restrict__ src, float* __restrict__ dst,
                             int K, int total4)
{
    int idx = blockIdx.x*256 + threadIdx.x;
    if (idx >= total4) return;
    int kq = K >> 2;
    int row = idx / kq, c4 = idx - row*kq;
    int col = c4*4;
    float4 v = *(const float4*)(src + (long)row*K + col);
    long base = (long)row*K + (col & ~31) + ((col & 31) >> 2);
    dst[base] = v.x; dst[base+8] = v.y; dst[base+16] = v.z; dst[base+24] = v.w;
}

__global__ void bcat_kernel(const float* __restrict__ a, const float* __restrict__ b,
                            const float* __restrict__ c, float* __restrict__ dst)
{
    int t = blockIdx.x*256 + threadIdx.x;
    dst[t] = (t < D_) ? a[t] : (t < 2*D_) ? b[t-D_] : c[t-2*D_];
}

// ---------------------------------------------------------------------------
// LayerNorm (torch-style). PERM=true writes permuted column layout.
// ---------------------------------------------------------------------------
template<bool PERM>
__global__ void ln_kernel(const float* __restrict__ x,
                          const float* __restrict__ alpha,
                          const float* __restrict__ beta,
                          float* __restrict__ y)
{
    __shared__ float s1[8], s2[8];
    long row = blockIdx.x;
    const float4* xr = (const float4*)(x + row*(long)D_);
    float4 v = xr[threadIdx.x];
    float sum = v.x+v.y+v.z+v.w;
    float sq  = v.x*v.x+v.y*v.y+v.z*v.z+v.w*v.w;
    int lane = threadIdx.x & 31, w = threadIdx.x >> 5;
    sum = warpRedSum(sum); sq = warpRedSum(sq);
    if (lane==0){ s1[w]=sum; s2[w]=sq; }
    __syncthreads();
    if (w==0){
        float a = (lane<8)? s1[lane] : 0.f;
        float b = (lane<8)? s2[lane] : 0.f;
        a = warpRedSum(a); b = warpRedSum(b);
        if (lane==0){ s1[0]=a; s2[0]=b; }
    }
    __syncthreads();
    float mean = s1[0] * (1.f/D_);
    float var  = (s2[0] - (float)D_*mean*mean) * (1.f/(D_-1));
    var = fmaxf(var, 0.f);
    float inv = alpha[0] / (sqrtf(var) + 1e-6f);
    float c   = beta[0];
    float4 o;
    o.x=(v.x-mean)*inv+c; o.y=(v.y-mean)*inv+c;
    o.z=(v.z-mean)*inv+c; o.w=(v.w-mean)*inv+c;
    if (PERM){
        int col = threadIdx.x*4;
        float* base = y + row*(long)D_ + (col & ~31) + ((col & 31) >> 2);
        base[0] = o.x; base[8] = o.y; base[16] = o.z; base[24] = o.w;
    } else {
        ((float4*)(y + row*(long)D_))[threadIdx.x] = o;
    }
}

// ---------------------------------------------------------------------------
// Fused flash attention over permuted-D Q/K/V in g_qkv.
// Contraction positions are natural (permuted layout == fragment order).
// ---------------------------------------------------------------------------
#define KSTR  68
#define VTSTR 132
#define PSTR  132

#define OFF_K    0                       // 2 * 128*68 = 17408
#define OFF_VR   17408                   // 128*68 = 8704
#define OFF_VT   (OFF_VR + 8704)         // 64*132 = 8448
#define OFF_P    (OFF_VT + 8448)         // 128*132 = 16896
#define OFF_MUL  (OFF_P + 16896)
#define OFF_ADD  (OFF_MUL + 128)
#define FA_SMEMF (OFF_ADD + 128)         // 51712 floats = 206848 B

__global__ __launch_bounds__(256, 1) void flash_kernel(
    const float* __restrict__ QKV, const int* __restrict__ mask,
    float* __restrict__ O)
{
    extern __shared__ float sm[];
    const int tid = threadIdx.x, lane = tid & 31, w = tid >> 5;
    const int g = lane >> 2, tg = lane & 3;
    const int bh = blockIdx.y, b = bh >> 4, h = bh & 15;
    const int hcol = h * DK_;
    const int qbase = blockIdx.x * 128;
    const long rowB = (long)b * S_;

    uint32_t sbase = (uint32_t)__cvta_generic_to_shared(sm);

    // ---- Q fragments from permuted gmem (float4 loads), scaled by 1/8 ----
    uint32_t qa[8][4];
    {
        const float* q0 = QKV + (rowB + qbase + w*16 + g)*(long)D3_ + hcol;
        const float* q8 = q0 + 8*(long)D3_;
        float4 qf0[4], qf8[4];
        #pragma unroll
        for (int f=0; f<4; f++){
            int off = (f>>1)*32 + tg*8 + (f&1)*4;
            qf0[f] = *(const float4*)(q0 + off);
            qf8[f] = *(const float4*)(q8 + off);
        }
        #pragma unroll
        for (int s=0; s<8; s++){
            int f = (s>>2)*2 + ((s&3)>>1);
            int c0 = 2*(s&1);
            qa[s][0] = __float_as_uint(fc(qf0[f], c0  )*0.125f);
            qa[s][1] = __float_as_uint(fc(qf8[f], c0  )*0.125f);
            qa[s][2] = __float_as_uint(fc(qf0[f], c0+1)*0.125f);
            qa[s][3] = __float_as_uint(fc(qf8[f], c0+1)*0.125f);
        }
    }

    // ---- issue K0 + V0 ----
    {
        const float* Kg = QKV + rowB*D3_ + D_   + hcol;
        const float* Vg = QKV + rowB*D3_ + 2*D_ + hcol;
        #pragma unroll
        for (int i=0;i<8;i++){
            int idx = i*256 + tid, r = idx >> 4, c4 = idx & 15;
            cpa16(sbase + (uint32_t)((OFF_K + r*KSTR + c4*4)*4),
                  Kg + (long)r*D3_ + c4*4);
        }
        #pragma unroll
        for (int i=0;i<8;i++){
            int idx = i*256 + tid, r = idx >> 4, c4 = idx & 15;
            cpa16(sbase + (uint32_t)((OFF_VR + r*KSTR + c4*4)*4),
                  Vg + (long)r*D3_ + c4*4);
        }
        cpcommit();
    }

    float o_acc[8][4];
    #pragma unroll
    for (int j=0;j<8;j++){ o_acc[j][0]=0.f;o_acc[j][1]=0.f;o_acc[j][2]=0.f;o_acc[j][3]=0.f; }
    float m0 = -__int_as_float(0x7f800000), m1 = m0;
    float l0 = 0.f, l1 = 0.f;

    const int NT = S_ / 128;
    for (int it = 0; it < NT; it++){
        const int buf = it & 1;
        __syncthreads();

        if (it+1 < NT){
            const float* Kg = QKV + (rowB + (it+1)*128)*(long)D3_ + D_ + hcol;
            #pragma unroll
            for (int i=0;i<8;i++){
                int idx = i*256 + tid, r = idx >> 4, c4 = idx & 15;
                cpa16(sbase + (uint32_t)((OFF_K + (buf^1)*8704 + r*KSTR + c4*4)*4),
                      Kg + (long)r*D3_ + c4*4);
            }
        }
        cpcommit();
        cpwait1();

        if (tid < 128){
            int mv = mask[rowB + it*128 + tid];
            sm[OFF_MUL + tid] = mv ? 1.f : 0.f;
            sm[OFF_ADD + tid] = mv ? 0.f : -1e9f;
        }
        // transpose Vraw(kv, permuted-d) -> vt(d, permuted-kv)
        #pragma unroll
        for (int i=0;i<8;i++){
            int idx = i*256 + tid, kv = idx & 127, d4 = idx >> 7;
            float4 vv = *(const float4*)(sm + OFF_VR + kv*KSTR + d4*4);
            int pkv = (kv & ~31) + ((kv & 3) << 3) + ((kv & 31) >> 2);
            #pragma unroll
            for (int cc=0; cc<4; cc++){
                int p = d4*4 + cc;
                int d = (p & ~31) + ((p & 7) << 2) + ((p >> 3) & 3);
                sm[OFF_VT + d*VTSTR + pkv] = fc(vv, cc);
            }
        }
        __syncthreads();

        if (it+1 < NT){
            const float* Vg = QKV + (rowB + (it+1)*128)*(long)D3_ + 2*D_ + hcol;
            #pragma unroll
            for (int i=0;i<8;i++){
                int idx = i*256 + tid, r = idx >> 4, c4 = idx & 15;
                cpa16(sbase + (uint32_t)((OFF_VR + r*KSTR + c4*4)*4),
                      Vg + (long)r*D3_ + c4*4);
            }
        }
        cpcommit();

        // ---- scores: S = Q K^T, float4 B-fragments ----
        float c[16][4];
        const float* Ksb = sm + OFF_K + buf*8704;
        #pragma unroll
        for (int j=0;j<16;j++){
            c[j][0]=0.f;c[j][1]=0.f;c[j][2]=0.f;c[j][3]=0.f;
            const float* kr = Ksb + (j*8+g)*KSTR + tg*8;
            float4 kf[4];
            kf[0] = *(const float4*)(kr);
            kf[1] = *(const float4*)(kr+4);
            kf[2] = *(const float4*)(kr+32);
            kf[3] = *(const float4*)(kr+36);
            #pragma unroll
            for (int s=0; s<8; s++){
                int f = (s>>2)*2 + ((s&3)>>1);
                int c0 = 2*(s&1);
                uint32_t bb[2];
                bb[0] = __float_as_uint(fc(kf[f], c0  ));
                bb[1] = __float_as_uint(fc(kf[f], c0+1));
                mma8(c[j], qa[s], bb);
            }
        }

        // ---- mask + online softmax ----
        float mx0 = -3.0e38f, mx1 = -3.0e38f;
        #pragma unroll
        for (int j=0;j<16;j++){
            int cc = j*8 + 2*tg;
            float mu0 = sm[OFF_MUL+cc], mu1 = sm[OFF_MUL+cc+1];
            float ad0 = sm[OFF_ADD+cc], ad1 = sm[OFF_ADD+cc+1];
            c[j][0] = fmaf(c[j][0], mu0, ad0);
            c[j][1] = fmaf(c[j][1], mu1, ad1);
            c[j][2] = fmaf(c[j][2], mu0, ad0);
            c[j][3] = fmaf(c[j][3], mu1, ad1);
            mx0 = fmaxf(mx0, fmaxf(c[j][0], c[j][1]));
            mx1 = fmaxf(mx1, fmaxf(c[j][2], c[j][3]));
        }
        mx0 = fmaxf(mx0, __shfl_xor_sync(0xffffffffu, mx0, 1));
        mx0 = fmaxf(mx0, __shfl_xor_sync(0xffffffffu, mx0, 2));
        mx1 = fmaxf(mx1, __shfl_xor_sync(0xffffffffu, mx1, 1));
        mx1 = fmaxf(mx1, __shfl_xor_sync(0xffffffffu, mx1, 2));

        float nm0 = fmaxf(m0, mx0), nm1 = fmaxf(m1, mx1);
        float cr0 = __expf(m0 - nm0), cr1 = __expf(m1 - nm1);
        float s0 = 0.f, s1 = 0.f;
        #pragma unroll
        for (int j=0;j<16;j++){
            c[j][0] = __expf(c[j][0] - nm0);
            c[j][1] = __expf(c[j][1] - nm0);
            c[j][2] = __expf(c[j][2] - nm1);
            c[j][3] = __expf(c[j][3] - nm1);
            s0 += c[j][0] + c[j][1];
            s1 += c[j][2] + c[j][3];
        }
        s0 += __shfl_xor_sync(0xffffffffu, s0, 1);
        s0 += __shfl_xor_sync(0xffffffffu, s0, 2);
        s1 += __shfl_xor_sync(0xffffffffu, s1, 1);
        s1 += __shfl_xor_sync(0xffffffffu, s1, 2);
        l0 = l0*cr0 + s0;  l1 = l1*cr1 + s1;
        m0 = nm0;          m1 = nm1;
        #pragma unroll
        for (int j=0;j<8;j++){
            o_acc[j][0]*=cr0; o_acc[j][1]*=cr0; o_acc[j][2]*=cr1; o_acc[j][3]*=cr1;
        }

        // ---- write P to smem (warp-private rows) ----
        {
            float* Pr0 = sm + OFF_P + (w*16+g)*PSTR + 2*tg;
            float* Pr8 = Pr0 + 8*PSTR;
            #pragma unroll
            for (int j=0;j<16;j++){
                *(float2*)(Pr0 + j*8) = make_float2(c[j][0], c[j][1]);
                *(float2*)(Pr8 + j*8) = make_float2(c[j][2], c[j][3]);
            }
        }
        __syncwarp();

        // ---- O += P @ V, float4 B-fragments from permuted vt ----
        {
            const float* Pw = sm + OFF_P + (w*16)*PSTR;
            #pragma unroll
            for (int bb4=0; bb4<4; bb4++){
                float4 vr[8][2];
                #pragma unroll
                for (int jo=0; jo<8; jo++){
                    const float* vb = sm + OFF_VT + (jo*8+g)*VTSTR + bb4*32 + tg*8;
                    vr[jo][0] = *(const float4*)(vb);
                    vr[jo][1] = *(const float4*)(vb+4);
                }
                #pragma unroll
                for (int mq=0; mq<4; mq++){
                    int kk = bb4*4 + mq;
                    uint32_t a[4];
                    a[0] = __float_as_uint(Pw[ g    *PSTR + kk*8+tg  ]);
                    a[1] = __float_as_uint(Pw[(g+8)*PSTR + kk*8+tg  ]);
                    a[2] = __float_as_uint(Pw[ g    *PSTR + kk*8+tg+4]);
                    a[3] = __float_as_uint(Pw[(g+8)*PSTR + kk*8+tg+4]);
                    int hh = mq>>1, c0 = 2*(mq&1);
                    #pragma unroll
                    for (int jo=0; jo<8; jo++){
                        uint32_t bb[2];
                        bb[0] = __float_as_uint(fc(vr[jo][hh], c0  ));
                        bb[1] = __float_as_uint(fc(vr[jo][hh], c0+1));
                        mma8(o_acc[jo], a, bb);
                    }
                }
            }
        }
    }

    // ---- epilogue: O / l, permuted-D store ----
    float inv0 = 1.f / l0, inv1 = 1.f / l1;
    float* o0 = O + (rowB + qbase + w*16 + g)*(long)D_;
    float* o8 = o0 + 8*(long)D_;
    #pragma unroll
    for (int jo=0; jo<8; jo++){
        int col = hcol + jo*8 + 2*tg;
        int p = permc(col);
        o0[p] = o_acc[jo][0]*inv0; o0[p+8] = o_acc[jo][1]*inv0;
        o8[p] = o_acc[jo][2]*inv1; o8[p+8] = o_acc[jo][3]*inv1;
    }
}

// ---------------------------------------------------------------------------
// NT GEMM, tf32, cp.async double-buffered, permuted-K operands (float4 frags).
// PERMC: write C columns permuted (for consumption by the next GEMM).
// ---------------------------------------------------------------------------
template<int BM,int BN,int WR,int WC,bool HAS_BIAS,bool RELU,bool HAS_RESID,bool PERMC>
__global__ __launch_bounds__(WR*WC*32, 1) void gemm3(
    const float* __restrict__ A, int lda,
    const float* __restrict__ Bm, int ldb,
    float* __restrict__ C, int ldc,
    const float* __restrict__ bias, const float* __restrict__ resid,
    int K, float scale)
{
    constexpr int BK = 32, LDSW = 36;
    constexpr int NT = WR*WC*32;
    constexpr int WM = BM/WR, WN = BN/WC;
    constexpr int MF = WM/16, NF = WN/8;
    constexpr int ASZ = BM*LDSW, BSZ = BN*LDSW;

    extern __shared__ float smemf[];
    float* As = smemf;
    float* Bs = smemf + 2*ASZ;

    int tid = threadIdx.x, lane = tid & 31, warp = tid >> 5;
    int g = lane >> 2, tg = lane & 3;
    int wm = warp / WC, wn = warp % WC;
    int m0 = blockIdx.y * BM, n0 = blockIdx.x * BN;

    uint32_t sbase = (uint32_t)__cvta_generic_to_shared(smemf);

    float acc[MF][NF][4];
    #pragma unroll
    for (int i=0;i<MF;i++)
        #pragma unroll
        for (int j=0;j<NF;j++)
            #pragma unroll
            for (int r=0;r<4;r++) acc[i][j][r] = 0.f;

    auto loadt = [&](int k0, int buf){
        #pragma unroll
        for (int i = 0; i < BM*8; i += NT){
            int idx = i + tid; int r = idx >> 3, c = idx & 7;
            cpa16(sbase + (uint32_t)((buf*ASZ + r*LDSW + c*4)*4),
                  A + (long)(m0+r)*lda + k0 + c*4);
        }
        #pragma unroll
        for (int i = 0; i < BN*8; i += NT){
            int idx = i + tid; int r = idx >> 3, c = idx & 7;
            cpa16(sbase + (uint32_t)((2*ASZ + buf*BSZ + r*LDSW + c*4)*4),
                  Bm + (long)(n0+r)*ldb + k0 + c*4);
        }
        cpcommit();
    };

    int nt = K / BK;
    loadt(0, 0);

    for (int k0 = 0; k0 < nt; k0++){
        int cur = k0 & 1;
        if (k0+1 < nt){
            loadt((k0+1)*BK, cur^1);
            cpwait1();
        } else {
            cpwait0();
        }
        __syncthreads();

        const float* Asb = As + cur*ASZ;
        const float* Bsb = Bs + cur*BSZ;

        #pragma unroll
        for (int half=0; half<2; half++){
            float4 af4[MF][2];
            #pragma unroll
            for (int im=0; im<MF; im++){
                int r = wm*WM + im*16 + g;
                af4[im][0] = *(const float4*)&Asb[ r   *LDSW + tg*8 + half*4];
                af4[im][1] = *(const float4*)&Asb[(r+8)*LDSW + tg*8 + half*4];
            }
            float4 bf4[NF];
            #pragma unroll
            for (int jn=0; jn<NF; jn++){
                int r = wn*WN + jn*8 + g;
                bf4[jn] = *(const float4*)&Bsb[r*LDSW + tg*8 + half*4];
            }
            #pragma unroll
            for (int s2=0; s2<2; s2++){
                uint32_t af[MF][4], bf[NF][2];
                #pragma unroll
                for (int im=0; im<MF; im++){
                    af[im][0] = __float_as_uint(fc(af4[im][0], 2*s2  ));
                    af[im][1] = __float_as_uint(fc(af4[im][1], 2*s2  ));
                    af[im][2] = __float_as_uint(fc(af4[im][0], 2*s2+1));
                    af[im][3] = __float_as_uint(fc(af4[im][1], 2*s2+1));
                }
                #pragma unroll
                for (int jn=0; jn<NF; jn++){
                    bf[jn][0] = __float_as_uint(fc(bf4[jn], 2*s2  ));
                    bf[jn][1] = __float_as_uint(fc(bf4[jn], 2*s2+1));
                }
                #pragma unroll
                for (int im=0; im<MF; im++)
                    #pragma unroll
                    for (int jn=0; jn<NF; jn++)
                        mma8(acc[im][jn], af[im], bf[jn]);
            }
        }
        __syncthreads();
    }

    #pragma unroll
    for (int im=0; im<MF; im++){
        int r0 = m0 + wm*WM + im*16 + g;
        #pragma unroll
        for (int jn=0; jn<NF; jn++){
            int c0 = n0 + wn*WN + jn*8 + tg*2;
            float2 bv = HAS_BIAS ? *(const float2*)(bias + c0) : make_float2(0.f,0.f);
            float2 v0, v1;
            v0.x = acc[im][jn][0]*scale + bv.x;
            v0.y = acc[im][jn][1]*scale + bv.y;
            v1.x = acc[im][jn][2]*scale + bv.x;
            v1.y = acc[im][jn][3]*scale + bv.y;
            if (RELU){
                v0.x = fmaxf(v0.x,0.f); v0.y = fmaxf(v0.y,0.f);
                v1.x = fmaxf(v1.x,0.f); v1.y = fmaxf(v1.y,0.f);
            }
            if (HAS_RESID){
                float2 ra = *(const float2*)(resid + (long)r0*ldc + c0);
                float2 rb = *(const float2*)(resid + (long)(r0+8)*ldc + c0);
                v0.x += ra.x; v0.y += ra.y; v1.x += rb.x; v1.y += rb.y;
            }
            if (PERMC){
                int p = permc(c0);          // c0 even -> second elem at p+8
                C[(long)r0*ldc + p]       = v0.x;
                C[(long)r0*ldc + p+8]     = v0.y;
                C[(long)(r0+8)*ldc + p]   = v1.x;
                C[(long)(r0+8)*ldc + p+8] = v1.y;
            } else {
                *(float2*)(C + (long)r0*ldc + c0)     = v0;
                *(float2*)(C + (long)(r0+8)*ldc + c0) = v1;
            }
        }
    }
}

// ---------------------------------------------------------------------------
// Launch
// ---------------------------------------------------------------------------
extern "C" void kernel_launch(void* const* d_in, const int* in_sizes, int n_in,
                              void* d_out, int out_size)
{
    const float* x    = (const float*)d_in[0];
    const int*   mask = (const int*)  d_in[1];
    const float* wq = (const float*)d_in[2];  const float* bq = (const float*)d_in[3];
    const float* wk = (const float*)d_in[4];  const float* bk = (const float*)d_in[5];
    const float* wv = (const float*)d_in[6];  const float* bv = (const float*)d_in[7];
    const float* wo = (const float*)d_in[8];  const float* bo = (const float*)d_in[9];
    const float* w1 = (const float*)d_in[10]; const float* b1 = (const float*)d_in[11];
    const float* w2 = (const float*)d_in[12]; const float* b2 = (const float*)d_in[13];
    const float* a1 = (const float*)d_in[14]; const float* c1 = (const float*)d_in[15];
    const float* a2 = (const float*)d_in[16]; const float* c2 = (const float*)d_in[17];
    float* out = (float*)d_out;

    void* p;
    float *xn,*qkv,*ao,*h,*hn,*f1,*wqkv_p,*wo_p,*w1_p,*w2_p,*bqkv;
    cudaGetSymbolAddress(&p, g_xn);   xn = (float*)p;
    cudaGetSymbolAddress(&p, g_qkv);  qkv = (float*)p;
    cudaGetSymbolAddress(&p, g_ao);   ao = (float*)p;
    cudaGetSymbolAddress(&p, g_h );   h  = (float*)p;
    cudaGetSymbolAddress(&p, g_hn);   hn = (float*)p;
    cudaGetSymbolAddress(&p, g_f1);   f1 = (float*)p;
    cudaGetSymbolAddress(&p, g_wqkv); wqkv_p = (float*)p;
    cudaGetSymbolAddress(&p, g_wo);   wo_p = (float*)p;
    cudaGetSymbolAddress(&p, g_w1);   w1_p = (float*)p;
    cudaGetSymbolAddress(&p, g_w2);   w2_p = (float*)p;
    cudaGetSymbolAddress(&p, g_bqkv); bqkv = (float*)p;

    constexpr int SMEM_BIG = (2*128 + 2*256)*36*4;   // 110592 B
    constexpr int SMEM_FA  = FA_SMEMF*4;             // 206848 B

    cudaFuncSetAttribute((const void*)gemm3<128,256,2,4,true ,false,false,true >,
                         cudaFuncAttributeMaxDynamicSharedMemorySize, SMEM_BIG);
    cudaFuncSetAttribute((const void*)gemm3<128,256,2,4,true ,false,true ,false>,
                         cudaFuncAttributeMaxDynamicSharedMemorySize, SMEM_BIG);
    cudaFuncSetAttribute((const void*)gemm3<128,256,2,4,true ,true ,false,true >,
                         cudaFuncAttributeMaxDynamicSharedMemorySize, SMEM_BIG);
    cudaFuncSetAttribute((const void*)flash_kernel,
                         cudaFuncAttributeMaxDynamicSharedMemorySize, SMEM_FA);

    // 0) weight permutes + bias concat
    wperm_kernel<<<(D_*D_/4+255)/256,256>>>(wq, wqkv_p,            D_, D_*D_/4);
    wperm_kernel<<<(D_*D_/4+255)/256,256>>>(wk, wqkv_p + D_*D_,    D_, D_*D_/4);
    wperm_kernel<<<(D_*D_/4+255)/256,256>>>(wv, wqkv_p + 2*D_*D_,  D_, D_*D_/4);
    wperm_kernel<<<(D_*D_/4+255)/256,256>>>(wo, wo_p,              D_, D_*D_/4);
    wperm_kernel<<<(DFF_*D_/4+255)/256,256>>>(w1, w1_p,            D_, DFF_*D_/4);
    wperm_kernel<<<(D_*DFF_/4+255)/256,256>>>(w2, w2_p,            DFF_, D_*DFF_/4);
    bcat_kernel<<<D3_/256,256>>>(bq, bk, bv, bqkv);

    // 1) LN1 -> permuted xn
    ln_kernel<true><<<M_, 256>>>(x, a1, c1, xn);

    // 2) fused QKV projection: [8192,1024] @ [3072,1024]^T -> permuted qkv
    dim3 gq(D3_/256, M_/128, 1);
    gemm3<128,256,2,4,true,false,false,true><<<gq,256,SMEM_BIG>>>(
        xn, D_, wqkv_p, D_, qkv, D3_, bqkv, nullptr, D_, 1.f);

    // 3) fused flash attention -> permuted ao
    flash_kernel<<<dim3(S_/128, B_*H_), 256, SMEM_FA>>>(qkv, mask, ao);

    // 4) O projection + residual x -> natural h
    dim3 gp(D_/256, M_/128, 1);
    gemm3<128,256,2,4,true,false,true,false><<<gp,256,SMEM_BIG>>>(
        ao, D_, wo_p, D_, h, D_, bo, x, D_, 1.f);

    // 5) LN2 -> permuted hn
    ln_kernel<true><<<M_, 256>>>(h, a2, c2, hn);

    // 6) FFN1 + ReLU -> permuted f1
    dim3 gf1(DFF_/256, M_/128, 1);
    gemm3<128,256,2,4,true,true,false,true><<<gf1,256,SMEM_BIG>>>(
        hn, D_, w1_p, D_, f1, DFF_, b1, nullptr, D_, 1.f);

    // 7) FFN2 + residual h -> natural out
    gemm3<128,256,2,4,true,false,true,false><<<gp,256,SMEM_BIG>>>(
        f1, DFF_, w2_p, DFF_, out, D_, b2, h, DFF_, 1.f);
}

// round 5
// speedup vs baseline: 1.1891x; 1.1891x over previous
#include <cuda_runtime.h>
#include <cstdint>

// Problem constants
#define B_    4
#define S_    2048
#define D_    1024
#define H_    16
#define DK_   64
#define DFF_  4096
#define M_    (B_*S_)   // 8192 rows
#define D3_   (3*D_)    // 3072

// ---------------------------------------------------------------------------
// Static device scratch (allocation-free rule)
// ---------------------------------------------------------------------------
__device__ float g_xn[M_*D_];               // LN1 output
__device__ float g_qkv[M_*D3_];             // fused QKV output
__device__ float g_ao[M_*D_];               // attention output
__device__ float g_h [M_*D_];               // residual 1
__device__ float g_hn[M_*D_];               // LN2 output
__device__ float g_f1[M_*DFF_];             // FFN hidden
__device__ float g_wqkv[D3_*D_];            // concat QKV weights
__device__ float g_bqkv[D3_];               // concat QKV biases

// ---------------------------------------------------------------------------
// Helpers
// ---------------------------------------------------------------------------
__device__ __forceinline__ float warpRedSum(float v){
    #pragma unroll
    for (int o=16;o;o>>=1) v += __shfl_xor_sync(0xffffffffu, v, o);
    return v;
}

__device__ __forceinline__ void mma8(float c[4], const uint32_t a[4], const uint32_t b[2]){
    asm volatile(
        "mma.sync.aligned.m16n8k8.row.col.f32.tf32.tf32.f32 "
        "{%0,%1,%2,%3}, {%4,%5,%6,%7}, {%8,%9}, {%0,%1,%2,%3};\n"
        : "+f"(c[0]), "+f"(c[1]), "+f"(c[2]), "+f"(c[3])
        : "r"(a[0]), "r"(a[1]), "r"(a[2]), "r"(a[3]),
          "r"(b[0]), "r"(b[1]));
}

__device__ __forceinline__ void cpa16(uint32_t dst, const void* src){
    asm volatile("cp.async.cg.shared.global [%0], [%1], 16;\n" :: "r"(dst), "l"(src));
}
__device__ __forceinline__ void cpcommit(){ asm volatile("cp.async.commit_group;\n"); }
__device__ __forceinline__ void cpwait0(){ asm volatile("cp.async.wait_group 0;\n"); }
__device__ __forceinline__ void cpwait2(){ asm volatile("cp.async.wait_group 2;\n"); }

// ---------------------------------------------------------------------------
// Weight / bias concat (plain copies)
// ---------------------------------------------------------------------------
__global__ void wcat_kernel(const float* __restrict__ a, const float* __restrict__ b,
                            const float* __restrict__ c, float* __restrict__ dst)
{
    long i = (long)blockIdx.x*256 + threadIdx.x;     // float4 index
    const long n = (long)D_*D_/4;
    float4 v;
    if (i < n)        v = ((const float4*)a)[i];
    else if (i < 2*n) v = ((const float4*)b)[i-n];
    else              v = ((const float4*)c)[i-2*n];
    ((float4*)dst)[i] = v;
}

__global__ void bcat_kernel(const float* __restrict__ a, const float* __restrict__ b,
                            const float* __restrict__ c, float* __restrict__ dst)
{
    int t = blockIdx.x*256 + threadIdx.x;
    dst[t] = (t < D_) ? a[t] : (t < 2*D_) ? b[t-D_] : c[t-2*D_];
}

// ---------------------------------------------------------------------------
// LayerNorm (torch-style: a*(x-mean)/(std+eps)+c, std unbiased, eps on std)
// ---------------------------------------------------------------------------
__global__ void ln_kernel(const float* __restrict__ x,
                          const float* __restrict__ alpha,
                          const float* __restrict__ beta,
                          float* __restrict__ y)
{
    __shared__ float s1[8], s2[8];
    long row = blockIdx.x;
    const float4* xr = (const float4*)(x + row*(long)D_);
    float4 v = xr[threadIdx.x];
    float sum = v.x+v.y+v.z+v.w;
    float sq  = v.x*v.x+v.y*v.y+v.z*v.z+v.w*v.w;
    int lane = threadIdx.x & 31, w = threadIdx.x >> 5;
    sum = warpRedSum(sum); sq = warpRedSum(sq);
    if (lane==0){ s1[w]=sum; s2[w]=sq; }
    __syncthreads();
    if (w==0){
        float a = (lane<8)? s1[lane] : 0.f;
        float b = (lane<8)? s2[lane] : 0.f;
        a = warpRedSum(a); b = warpRedSum(b);
        if (lane==0){ s1[0]=a; s2[0]=b; }
    }
    __syncthreads();
    float mean = s1[0] * (1.f/D_);
    float var  = (s2[0] - (float)D_*mean*mean) * (1.f/(D_-1));
    var = fmaxf(var, 0.f);
    float inv = alpha[0] / (sqrtf(var) + 1e-6f);
    float c   = beta[0];
    float4 o;
    o.x=(v.x-mean)*inv+c; o.y=(v.y-mean)*inv+c;
    o.z=(v.z-mean)*inv+c; o.w=(v.w-mean)*inv+c;
    ((float4*)(y + row*(long)D_))[threadIdx.x] = o;
}

// ---------------------------------------------------------------------------
// Fused flash attention over fused QKV [M, 3072].
// Per CTA: 128 Q rows of one (b,h). K double-buffered (stride 68),
// V double-buffered (stride 72, used directly as col-major mma B operand —
// no transpose), mask double-buffered one tile ahead.
// ONE __syncthreads per KV tile.
// ---------------------------------------------------------------------------
#define KSTR 68
#define VSTR 72
#define PSTR 132

#define OFF_K    0                         // 2 * 128*68 = 17408
#define OFF_V    17408                     // 2 * 128*72 = 18432
#define OFF_P    (OFF_V + 18432)           // 128*132 = 16896
#define OFF_MUL  (OFF_P + 16896)           // 2*128
#define OFF_ADD  (OFF_MUL + 256)           // 2*128
#define FA_SMEMF (OFF_ADD + 256)           // 53248 floats = 212992 B

__global__ __launch_bounds__(256, 1) void flash_kernel(
    const float* __restrict__ QKV, const int* __restrict__ mask,
    float* __restrict__ O)
{
    extern __shared__ float sm[];
    const int tid = threadIdx.x, lane = tid & 31, w = tid >> 5;
    const int g = lane >> 2, tg = lane & 3;
    const int bh = blockIdx.y, b = bh >> 4, h = bh & 15;
    const int hcol = h * DK_;
    const int qbase = blockIdx.x * 128;
    const long rowB = (long)b * S_;

    uint32_t sbase = (uint32_t)__cvta_generic_to_shared(sm);

    // ---- Q fragments (row-major A), pre-scaled by 1/sqrt(64) ----
    uint32_t qa[8][4];
    {
        const float* q0 = QKV + (rowB + qbase + w*16 + g)*(long)D3_ + hcol;
        const float* q8 = q0 + 8*(long)D3_;
        #pragma unroll
        for (int ks=0; ks<8; ks++){
            qa[ks][0] = __float_as_uint(q0[ks*8+tg  ]*0.125f);
            qa[ks][1] = __float_as_uint(q8[ks*8+tg  ]*0.125f);
            qa[ks][2] = __float_as_uint(q0[ks*8+tg+4]*0.125f);
            qa[ks][3] = __float_as_uint(q8[ks*8+tg+4]*0.125f);
        }
    }

    // ---- prologue: mask buf0 + issue K0,V0 (group 0) ----
    if (tid < 128){
        int mv = mask[rowB + tid];
        sm[OFF_MUL + tid] = mv ? 1.f : 0.f;
        sm[OFF_ADD + tid] = mv ? 0.f : -1e9f;
    }
    {
        const float* Kg = QKV + rowB*D3_ + D_   + hcol;
        const float* Vg = QKV + rowB*D3_ + 2*D_ + hcol;
        #pragma unroll
        for (int i=0;i<8;i++){
            int idx = i*256 + tid, r = idx >> 4, c4 = idx & 15;
            cpa16(sbase + (uint32_t)((OFF_K + r*KSTR + c4*4)*4),
                  Kg + (long)r*D3_ + c4*4);
        }
        #pragma unroll
        for (int i=0;i<8;i++){
            int idx = i*256 + tid, r = idx >> 4, c4 = idx & 15;
            cpa16(sbase + (uint32_t)((OFF_V + r*VSTR + c4*4)*4),
                  Vg + (long)r*D3_ + c4*4);
        }
        cpcommit();
    }

    float o_acc[8][4];
    #pragma unroll
    for (int j=0;j<8;j++){ o_acc[j][0]=0.f;o_acc[j][1]=0.f;o_acc[j][2]=0.f;o_acc[j][3]=0.f; }
    float m0 = -__int_as_float(0x7f800000), m1 = m0;
    float l0 = 0.f, l1 = 0.f;

    const int NT = S_ / 128;   // 16
    for (int it = 0; it < NT; it++){
        const int mb = it & 1;
        cpwait0();                    // K/V tile 'it' arrived
        __syncthreads();              // visibility + WAR (all warps past it-1)

        // issue K/V for it+1 + mask buf for it+1
        if (it+1 < NT){
            const int nb = (it+1) & 1;
            const float* Kg = QKV + (rowB + (it+1)*128)*(long)D3_ + D_   + hcol;
            const float* Vg = QKV + (rowB + (it+1)*128)*(long)D3_ + 2*D_ + hcol;
            #pragma unroll
            for (int i=0;i<8;i++){
                int idx = i*256 + tid, r = idx >> 4, c4 = idx & 15;
                cpa16(sbase + (uint32_t)((OFF_K + nb*8704 + r*KSTR + c4*4)*4),
                      Kg + (long)r*D3_ + c4*4);
            }
            #pragma unroll
            for (int i=0;i<8;i++){
                int idx = i*256 + tid, r = idx >> 4, c4 = idx & 15;
                cpa16(sbase + (uint32_t)((OFF_V + nb*9216 + r*VSTR + c4*4)*4),
                      Vg + (long)r*D3_ + c4*4);
            }
            cpcommit();
            if (tid < 128){
                int mv = mask[rowB + (it+1)*128 + tid];
                sm[OFF_MUL + nb*128 + tid] = mv ? 1.f : 0.f;
                sm[OFF_ADD + nb*128 + tid] = mv ? 0.f : -1e9f;
            }
        }

        // ---- scores: S = Q K^T (16 q rows per warp x 128 kv) ----
        float c[16][4];
        #pragma unroll
        for (int j=0;j<16;j++){ c[j][0]=0.f;c[j][1]=0.f;c[j][2]=0.f;c[j][3]=0.f; }
        const float* Ksb = sm + OFF_K + mb*8704;
        #pragma unroll
        for (int ks=0; ks<8; ks++){
            #pragma unroll
            for (int j=0;j<16;j++){
                uint32_t bb[2];
                bb[0] = __float_as_uint(Ksb[(j*8+g)*KSTR + ks*8+tg  ]);
                bb[1] = __float_as_uint(Ksb[(j*8+g)*KSTR + ks*8+tg+4]);
                mma8(c[j], qa[ks], bb);
            }
        }

        // ---- mask + online softmax ----
        const float* Mu = sm + OFF_MUL + mb*128;
        const float* Ad = sm + OFF_ADD + mb*128;
        float mx0 = -3.0e38f, mx1 = -3.0e38f;
        #pragma unroll
        for (int j=0;j<16;j++){
            int cc = j*8 + 2*tg;
            float mu0 = Mu[cc], mu1 = Mu[cc+1];
            float ad0 = Ad[cc], ad1 = Ad[cc+1];
            c[j][0] = fmaf(c[j][0], mu0, ad0);
            c[j][1] = fmaf(c[j][1], mu1, ad1);
            c[j][2] = fmaf(c[j][2], mu0, ad0);
            c[j][3] = fmaf(c[j][3], mu1, ad1);
            mx0 = fmaxf(mx0, fmaxf(c[j][0], c[j][1]));
            mx1 = fmaxf(mx1, fmaxf(c[j][2], c[j][3]));
        }
        mx0 = fmaxf(mx0, __shfl_xor_sync(0xffffffffu, mx0, 1));
        mx0 = fmaxf(mx0, __shfl_xor_sync(0xffffffffu, mx0, 2));
        mx1 = fmaxf(mx1, __shfl_xor_sync(0xffffffffu, mx1, 1));
        mx1 = fmaxf(mx1, __shfl_xor_sync(0xffffffffu, mx1, 2));

        float nm0 = fmaxf(m0, mx0), nm1 = fmaxf(m1, mx1);
        float cr0 = __expf(m0 - nm0), cr1 = __expf(m1 - nm1);
        float s0 = 0.f, s1 = 0.f;
        #pragma unroll
        for (int j=0;j<16;j++){
            c[j][0] = __expf(c[j][0] - nm0);
            c[j][1] = __expf(c[j][1] - nm0);
            c[j][2] = __expf(c[j][2] - nm1);
            c[j][3] = __expf(c[j][3] - nm1);
            s0 += c[j][0] + c[j][1];
            s1 += c[j][2] + c[j][3];
        }
        s0 += __shfl_xor_sync(0xffffffffu, s0, 1);
        s0 += __shfl_xor_sync(0xffffffffu, s0, 2);
        s1 += __shfl_xor_sync(0xffffffffu, s1, 1);
        s1 += __shfl_xor_sync(0xffffffffu, s1, 2);
        l0 = l0*cr0 + s0;  l1 = l1*cr1 + s1;
        m0 = nm0;          m1 = nm1;
        #pragma unroll
        for (int j=0;j<8;j++){
            o_acc[j][0]*=cr0; o_acc[j][1]*=cr0; o_acc[j][2]*=cr1; o_acc[j][3]*=cr1;
        }

        // ---- write P to smem (warp-private rows) ----
        {
            float* Pr0 = sm + OFF_P + (w*16+g)*PSTR + 2*tg;
            float* Pr8 = Pr0 + 8*PSTR;
            #pragma unroll
            for (int j=0;j<16;j++){
                *(float2*)(Pr0 + j*8) = make_float2(c[j][0], c[j][1]);
                *(float2*)(Pr8 + j*8) = make_float2(c[j][2], c[j][3]);
            }
        }
        __syncwarp();

        // ---- O += P @ V, V tile used directly as col-major B ----
        {
            const float* Pw = sm + OFF_P + (w*16)*PSTR;
            const float* Vb = sm + OFF_V + mb*9216;
            #pragma unroll
            for (int kk=0; kk<16; kk++){
                uint32_t a[4];
                a[0] = __float_as_uint(Pw[ g    *PSTR + kk*8+tg  ]);
                a[1] = __float_as_uint(Pw[(g+8)*PSTR + kk*8+tg  ]);
                a[2] = __float_as_uint(Pw[ g    *PSTR + kk*8+tg+4]);
                a[3] = __float_as_uint(Pw[(g+8)*PSTR + kk*8+tg+4]);
                const float* v0 = Vb + (kk*8+tg)*VSTR + g;
                const float* v4 = v0 + 4*VSTR;
                #pragma unroll
                for (int jo=0; jo<8; jo++){
                    uint32_t bb[2];
                    bb[0] = __float_as_uint(v0[jo*8]);
                    bb[1] = __float_as_uint(v4[jo*8]);
                    mma8(o_acc[jo], a, bb);
                }
            }
        }
    }

    // ---- epilogue: O / l ----
    float inv0 = 1.f / l0, inv1 = 1.f / l1;
    float* o0 = O + (rowB + qbase + w*16 + g)*(long)D_ + hcol + 2*tg;
    float* o8 = o0 + 8*(long)D_;
    #pragma unroll
    for (int jo=0; jo<8; jo++){
        *(float2*)(o0 + jo*8) = make_float2(o_acc[jo][0]*inv0, o_acc[jo][1]*inv0);
        *(float2*)(o8 + jo*8) = make_float2(o_acc[jo][2]*inv1, o_acc[jo][3]*inv1);
    }
}

// ---------------------------------------------------------------------------
// NT GEMM, tf32, 4-stage cp.async ring, ONE barrier per K-tile:
//   C[m,n] = scale * sum_k A[m,k]*B[n,k]  (+bias[n]) (+relu) (+resid[m,n])
// ---------------------------------------------------------------------------
template<int BM,int BN,int WR,int WC,bool HAS_BIAS,bool RELU,bool HAS_RESID>
__global__ __launch_bounds__(WR*WC*32, 1) void gemm4(
    const float* __restrict__ A, int lda,
    const float* __restrict__ Bm, int ldb,
    float* __restrict__ C, int ldc,
    const float* __restrict__ bias, const float* __restrict__ resid,
    int K, float scale)
{
    constexpr int BK = 32, LDSW = 36;
    constexpr int NTH = WR*WC*32;
    constexpr int WM = BM/WR, WN = BN/WC;
    constexpr int MF = WM/16, NF = WN/8;
    constexpr int ASZ = BM*LDSW, BSZ = BN*LDSW, SSZ = ASZ+BSZ;

    extern __shared__ float smemf[];

    int tid = threadIdx.x, lane = tid & 31, warp = tid >> 5;
    int g = lane >> 2, tg = lane & 3;
    int wm = warp / WC, wn = warp % WC;
    int m0 = blockIdx.y * BM, n0 = blockIdx.x * BN;

    uint32_t sbase = (uint32_t)__cvta_generic_to_shared(smemf);

    float acc[MF][NF][4];
    #pragma unroll
    for (int i=0;i<MF;i++)
        #pragma unroll
        for (int j=0;j<NF;j++)
            #pragma unroll
            for (int r=0;r<4;r++) acc[i][j][r] = 0.f;

    auto loadt = [&](int k0, int s){
        uint32_t stg = sbase + (uint32_t)(s*SSZ*4);
        #pragma unroll
        for (int i = 0; i < BM*8; i += NTH){
            int idx = i + tid; int r = idx >> 3, c = idx & 7;
            cpa16(stg + (uint32_t)((r*LDSW + c*4)*4),
                  A + (long)(m0+r)*lda + k0 + c*4);
        }
        #pragma unroll
        for (int i = 0; i < BN*8; i += NTH){
            int idx = i + tid; int r = idx >> 3, c = idx & 7;
            cpa16(stg + (uint32_t)((ASZ + r*LDSW + c*4)*4),
                  Bm + (long)(n0+r)*ldb + k0 + c*4);
        }
        cpcommit();
    };

    int nt = K / BK;                 // >= 32 at all call sites
    loadt(0, 0); loadt(BK, 1); loadt(2*BK, 2);

    for (int k0 = 0; k0 < nt; k0++){
        int cur = k0 & 3;
        cpwait2();                   // group k0 arrived (2 still in flight)
        __syncthreads();             // all warps done with stage (k0-1)&3
        if (k0+3 < nt) loadt((k0+3)*BK, (k0+3) & 3);
        else cpcommit();             // keep group accounting aligned

        const float* Asb = smemf + cur*SSZ;
        const float* Bsb = Asb + ASZ;

        #pragma unroll
        for (int ks = 0; ks < BK; ks += 8){
            uint32_t af[MF][4], bf[NF][2];
            #pragma unroll
            for (int im=0; im<MF; im++){
                int r = wm*WM + im*16 + g;
                af[im][0] = __float_as_uint(Asb[r*LDSW + ks+tg  ]);
                af[im][1] = __float_as_uint(Asb[(r+8)*LDSW + ks+tg  ]);
                af[im][2] = __float_as_uint(Asb[r*LDSW + ks+tg+4]);
                af[im][3] = __float_as_uint(Asb[(r+8)*LDSW + ks+tg+4]);
            }
            #pragma unroll
            for (int jn=0; jn<NF; jn++){
                int r = wn*WN + jn*8 + g;
                bf[jn][0] = __float_as_uint(Bsb[r*LDSW + ks+tg  ]);
                bf[jn][1] = __float_as_uint(Bsb[r*LDSW + ks+tg+4]);
            }
            #pragma unroll
            for (int im=0; im<MF; im++)
                #pragma unroll
                for (int jn=0; jn<NF; jn++)
                    mma8(acc[im][jn], af[im], bf[jn]);
        }
    }

    // epilogue (float2 stores)
    #pragma unroll
    for (int im=0; im<MF; im++){
        int r0 = m0 + wm*WM + im*16 + g;
        #pragma unroll
        for (int jn=0; jn<NF; jn++){
            int c0 = n0 + wn*WN + jn*8 + tg*2;
            float2 bv = HAS_BIAS ? *(const float2*)(bias + c0) : make_float2(0.f,0.f);
            float2 v0, v1;
            v0.x = acc[im][jn][0]*scale + bv.x;
            v0.y = acc[im][jn][1]*scale + bv.y;
            v1.x = acc[im][jn][2]*scale + bv.x;
            v1.y = acc[im][jn][3]*scale + bv.y;
            if (RELU){
                v0.x = fmaxf(v0.x,0.f); v0.y = fmaxf(v0.y,0.f);
                v1.x = fmaxf(v1.x,0.f); v1.y = fmaxf(v1.y,0.f);
            }
            if (HAS_RESID){
                float2 ra = *(const float2*)(resid + (long)r0*ldc + c0);
                float2 rb = *(const float2*)(resid + (long)(r0+8)*ldc + c0);
                v0.x += ra.x; v0.y += ra.y; v1.x += rb.x; v1.y += rb.y;
            }
            *(float2*)(C + (long)r0*ldc + c0)     = v0;
            *(float2*)(C + (long)(r0+8)*ldc + c0) = v1;
        }
    }
}

// ---------------------------------------------------------------------------
// Launch
// ---------------------------------------------------------------------------
extern "C" void kernel_launch(void* const* d_in, const int* in_sizes, int n_in,
                              void* d_out, int out_size)
{
    const float* x    = (const float*)d_in[0];
    const int*   mask = (const int*)  d_in[1];
    const float* wq = (const float*)d_in[2];  const float* bq = (const float*)d_in[3];
    const float* wk = (const float*)d_in[4];  const float* bk = (const float*)d_in[5];
    const float* wv = (const float*)d_in[6];  const float* bv = (const float*)d_in[7];
    const float* wo = (const float*)d_in[8];  const float* bo = (const float*)d_in[9];
    const float* w1 = (const float*)d_in[10]; const float* b1 = (const float*)d_in[11];
    const float* w2 = (const float*)d_in[12]; const float* b2 = (const float*)d_in[13];
    const float* a1 = (const float*)d_in[14]; const float* c1 = (const float*)d_in[15];
    const float* a2 = (const float*)d_in[16]; const float* c2 = (const float*)d_in[17];
    float* out = (float*)d_out;

    void* p;
    float *xn,*qkv,*ao,*h,*hn,*f1,*wqkv_c,*bqkv_c;
    cudaGetSymbolAddress(&p, g_xn);   xn = (float*)p;
    cudaGetSymbolAddress(&p, g_qkv);  qkv = (float*)p;
    cudaGetSymbolAddress(&p, g_ao);   ao = (float*)p;
    cudaGetSymbolAddress(&p, g_h );   h  = (float*)p;
    cudaGetSymbolAddress(&p, g_hn);   hn = (float*)p;
    cudaGetSymbolAddress(&p, g_f1);   f1 = (float*)p;
    cudaGetSymbolAddress(&p, g_wqkv); wqkv_c = (float*)p;
    cudaGetSymbolAddress(&p, g_bqkv); bqkv_c = (float*)p;

    constexpr int SMEM_G4 = 4*(128*36 + 256*36)*4;   // 221184 B
    constexpr int SMEM_FA = FA_SMEMF*4;              // 212992 B

    cudaFuncSetAttribute((const void*)gemm4<128,256,2,4,true ,false,false>,
                         cudaFuncAttributeMaxDynamicSharedMemorySize, SMEM_G4);
    cudaFuncSetAttribute((const void*)gemm4<128,256,2,4,true ,false,true >,
                         cudaFuncAttributeMaxDynamicSharedMemorySize, SMEM_G4);
    cudaFuncSetAttribute((const void*)gemm4<128,256,2,4,true ,true ,false>,
                         cudaFuncAttributeMaxDynamicSharedMemorySize, SMEM_G4);
    cudaFuncSetAttribute((const void*)flash_kernel,
                         cudaFuncAttributeMaxDynamicSharedMemorySize, SMEM_FA);

    // 0) weight + bias concat for fused QKV
    wcat_kernel<<<3*D_*D_/4/256, 256>>>(wq, wk, wv, wqkv_c);
    bcat_kernel<<<D3_/256, 256>>>(bq, bk, bv, bqkv_c);

    // 1) LN1
    ln_kernel<<<M_, 256>>>(x, a1, c1, xn);

    // 2) fused QKV projection: [8192,1024] @ [3072,1024]^T
    dim3 gq(D3_/256, M_/128, 1);
    gemm4<128,256,2,4,true,false,false><<<gq,256,SMEM_G4>>>(
        xn, D_, wqkv_c, D_, qkv, D3_, bqkv_c, nullptr, D_, 1.f);

    // 3) fused flash attention -> ao
    flash_kernel<<<dim3(S_/128, B_*H_), 256, SMEM_FA>>>(qkv, mask, ao);

    // 4) O projection + residual x
    dim3 gp(D_/256, M_/128, 1);
    gemm4<128,256,2,4,true,false,true><<<gp,256,SMEM_G4>>>(
        ao, D_, wo, D_, h, D_, bo, x, D_, 1.f);

    // 5) LN2
    ln_kernel<<<M_, 256>>>(h, a2, c2, hn);

    // 6) FFN1 + ReLU
    dim3 gf1(DFF_/256, M_/128, 1);
    gemm4<128,256,2,4,true,true,false><<<gf1,256,SMEM_G4>>>(
        hn, D_, w1, D_, f1, DFF_, b1, nullptr, D_, 1.f);

    // 7) FFN2 + residual h -> out
    gemm4<128,256,2,4,true,false,true><<<gp,256,SMEM_G4>>>(
        f1, DFF_, w2, DFF_, out, D_, b2, h, DFF_, 1.f);
}

// round 9
// speedup vs baseline: 2.1368x; 1.7970x over previous
#include <cuda_runtime.h>
#include <cuda_fp16.h>
#include <cstdint>

// Problem constants
#define B_    4
#define S_    2048
#define D_    1024
#define H_    16
#define DK_   64
#define DFF_  4096
#define M_    (B_*S_)   // 8192 rows
#define D3_   (3*D_)    // 3072

// ---------------------------------------------------------------------------
// Static device scratch (allocation-free rule)
// ---------------------------------------------------------------------------
__device__ __half g_xnh [M_*D_];
__device__ __half g_qkvh[M_*D3_];
__device__ __half g_aoh [M_*D_];
__device__ __half g_hnh [M_*D_];
__device__ __half g_f1h [M_*DFF_];
__device__ __half g_wqkvh[D3_*D_];
__device__ __half g_woh [D_*D_];
__device__ __half g_w1h [DFF_*D_];
__device__ __half g_w2h [D_*DFF_];
__device__ float  g_h   [M_*D_];
__device__ float  g_bqkv[D3_];

// ---------------------------------------------------------------------------
// Helpers
// ---------------------------------------------------------------------------
__device__ __forceinline__ float warpRedSum(float v){
    #pragma unroll
    for (int o=16;o;o>>=1) v += __shfl_xor_sync(0xffffffffu, v, o);
    return v;
}
__device__ __forceinline__ void mma16(float c[4], const uint32_t a[4], const uint32_t b[2]){
    asm volatile(
        "mma.sync.aligned.m16n8k16.row.col.f32.f16.f16.f32 "
        "{%0,%1,%2,%3}, {%4,%5,%6,%7}, {%8,%9}, {%0,%1,%2,%3};\n"
        : "+f"(c[0]), "+f"(c[1]), "+f"(c[2]), "+f"(c[3])
        : "r"(a[0]), "r"(a[1]), "r"(a[2]), "r"(a[3]),
          "r"(b[0]), "r"(b[1]));
}
__device__ __forceinline__ void ldsm4(uint32_t r[4], uint32_t a){
    asm volatile("ldmatrix.sync.aligned.m8n8.x4.shared.b16 {%0,%1,%2,%3}, [%4];"
        : "=r"(r[0]), "=r"(r[1]), "=r"(r[2]), "=r"(r[3]) : "r"(a));
}
__device__ __forceinline__ void ldsm4t(uint32_t r[4], uint32_t a){
    asm volatile("ldmatrix.sync.aligned.m8n8.x4.trans.shared.b16 {%0,%1,%2,%3}, [%4];"
        : "=r"(r[0]), "=r"(r[1]), "=r"(r[2]), "=r"(r[3]) : "r"(a));
}
__device__ __forceinline__ void cpa16(uint32_t dst, const void* src){
    asm volatile("cp.async.cg.shared.global [%0], [%1], 16;\n" :: "r"(dst), "l"(src));
}
__device__ __forceinline__ void cpcommit(){ asm volatile("cp.async.commit_group;\n"); }
__device__ __forceinline__ void cpwait0(){ asm volatile("cp.async.wait_group 0;\n"); }
__device__ __forceinline__ void cpwait1(){ asm volatile("cp.async.wait_group 1;\n"); }

// ---------------------------------------------------------------------------
// fp32 -> fp16 conversion / concat
// ---------------------------------------------------------------------------
__global__ void f2h_kernel(const float* __restrict__ src, __half* __restrict__ dst, long n4)
{
    long i = (long)blockIdx.x*256 + threadIdx.x;
    if (i >= n4) return;
    float4 v = ((const float4*)src)[i];
    __half2 h0 = __floats2half2_rn(v.x, v.y);
    __half2 h1 = __floats2half2_rn(v.z, v.w);
    uint2 u;
    u.x = *(uint32_t*)&h0; u.y = *(uint32_t*)&h1;
    ((uint2*)dst)[i] = u;
}
__global__ void bcat_kernel(const float* __restrict__ a, const float* __restrict__ b,
                            const float* __restrict__ c, float* __restrict__ dst)
{
    int t = blockIdx.x*256 + threadIdx.x;
    dst[t] = (t < D_) ? a[t] : (t < 2*D_) ? b[t-D_] : c[t-2*D_];
}

// ---------------------------------------------------------------------------
// LayerNorm (torch-style), fp16 output
// ---------------------------------------------------------------------------
__global__ void ln_kernel(const float* __restrict__ x,
                          const float* __restrict__ alpha,
                          const float* __restrict__ beta,
                          __half* __restrict__ y)
{
    __shared__ float s1[8], s2[8];
    long row = blockIdx.x;
    const float4* xr = (const float4*)(x + row*(long)D_);
    float4 v = xr[threadIdx.x];
    float sum = v.x+v.y+v.z+v.w;
    float sq  = v.x*v.x+v.y*v.y+v.z*v.z+v.w*v.w;
    int lane = threadIdx.x & 31, w = threadIdx.x >> 5;
    sum = warpRedSum(sum); sq = warpRedSum(sq);
    if (lane==0){ s1[w]=sum; s2[w]=sq; }
    __syncthreads();
    if (w==0){
        float a = (lane<8)? s1[lane] : 0.f;
        float b = (lane<8)? s2[lane] : 0.f;
        a = warpRedSum(a); b = warpRedSum(b);
        if (lane==0){ s1[0]=a; s2[0]=b; }
    }
    __syncthreads();
    float mean = s1[0] * (1.f/D_);
    float var  = (s2[0] - (float)D_*mean*mean) * (1.f/(D_-1));
    var = fmaxf(var, 0.f);
    float inv = alpha[0] / (sqrtf(var) + 1e-6f);
    float c   = beta[0];
    __half2 h0 = __floats2half2_rn((v.x-mean)*inv+c, (v.y-mean)*inv+c);
    __half2 h1 = __floats2half2_rn((v.z-mean)*inv+c, (v.w-mean)*inv+c);
    uint2 u; u.x = *(uint32_t*)&h0; u.y = *(uint32_t*)&h1;
    ((uint2*)(y + row*(long)D_))[threadIdx.x] = u;
}

// ---------------------------------------------------------------------------
// fp16 NT GEMM (m16n8k16), ldmatrix fragments, 3-stage cp.async ring (BK=64):
//   C[m,n] = sum_k A[m,k]*B[n,k] (+bias[n]) (+relu) (+resid[m,n])
// Row stride in smem: 72 halfs (144 B) -> ldmatrix conflict-free.
// ---------------------------------------------------------------------------
template<int BM,int BN,bool HAS_BIAS,bool RELU,bool HAS_RESID,bool OUT_HALF>
__global__ __launch_bounds__(256) void gemm_h(
    const __half* __restrict__ A, int lda,
    const __half* __restrict__ Bm, int ldb,
    void* __restrict__ Cv, int ldc,
    const float* __restrict__ bias, const float* __restrict__ resid,
    int K)
{
    constexpr int AW = 72;                     // halfs per smem row
    constexpr int STAGE_B = (BM+BN)*AW*2;      // bytes per stage

    extern __shared__ char smc[];
    uint32_t sb = (uint32_t)__cvta_generic_to_shared(smc);

    const int tid = threadIdx.x, lane = tid & 31, warp = tid >> 5;
    const int g = lane >> 2, tg = lane & 3, lq = lane & 7, lg = lane >> 3;
    const int wm = warp >> 2, wn = warp & 3;        // 2 x 4 warps
    const int m0 = blockIdx.y*BM, n0 = blockIdx.x*BN;

    float acc[4][8][4];
    #pragma unroll
    for (int i=0;i<4;i++)
        #pragma unroll
        for (int j=0;j<8;j++)
            #pragma unroll
            for (int r=0;r<4;r++) acc[i][j][r]=0.f;

    auto loadt = [&](int k0, int s){
        uint32_t st = sb + s*STAGE_B;
        #pragma unroll
        for (int i=0;i<BM*8;i+=256){
            int idx=i+tid, r=idx>>3, c=idx&7;
            cpa16(st + r*144 + c*16, A + (long)(m0+r)*lda + k0 + c*8);
        }
        uint32_t stB = st + BM*144;
        #pragma unroll
        for (int i=0;i<BN*8;i+=256){
            int idx=i+tid, r=idx>>3, c=idx&7;
            cpa16(stB + r*144 + c*16, Bm + (long)(n0+r)*ldb + k0 + c*8);
        }
        cpcommit();
    };

    const int nt = K/64;
    loadt(0,0); loadt(64,1);

    for (int ch=0; ch<nt; ch++){
        int s = ch%3;
        if (ch+2<nt) cpwait1(); else cpwait0();
        __syncthreads();
        if (ch+2<nt) loadt((ch+2)*64, (ch+2)%3);

        uint32_t sA = sb + s*STAGE_B;
        uint32_t sB = sA + BM*144;

        #pragma unroll
        for (int kb=0; kb<64; kb+=16){
            uint32_t a4[4][4], b4[4][4];
            #pragma unroll
            for (int im=0;im<4;im++){
                int row = wm*64 + im*16 + (lg&1)*8 + lq;
                int col = kb + (lg>>1)*8;
                ldsm4(a4[im], sA + (uint32_t)(row*AW + col)*2);
            }
            #pragma unroll
            for (int jp=0;jp<4;jp++){
                int row = wn*64 + jp*16 + (lg>>1)*8 + lq;
                int col = kb + (lg&1)*8;
                ldsm4(b4[jp], sB + (uint32_t)(row*AW + col)*2);
            }
            #pragma unroll
            for (int im=0;im<4;im++)
                #pragma unroll
                for (int jp=0;jp<4;jp++){
                    mma16(acc[im][2*jp],   a4[im], &b4[jp][0]);
                    mma16(acc[im][2*jp+1], a4[im], &b4[jp][2]);
                }
        }
    }

    // epilogue
    #pragma unroll
    for (int im=0;im<4;im++){
        int r0 = m0 + wm*64 + im*16 + g;
        #pragma unroll
        for (int jn=0;jn<8;jn++){
            int c0 = n0 + wn*64 + jn*8 + tg*2;
            float2 bv = HAS_BIAS ? *(const float2*)(bias + c0) : make_float2(0.f,0.f);
            float v00 = acc[im][jn][0] + bv.x;
            float v01 = acc[im][jn][1] + bv.y;
            float v10 = acc[im][jn][2] + bv.x;
            float v11 = acc[im][jn][3] + bv.y;
            if (RELU){
                v00=fmaxf(v00,0.f); v01=fmaxf(v01,0.f);
                v10=fmaxf(v10,0.f); v11=fmaxf(v11,0.f);
            }
            if (HAS_RESID){
                float2 ra = *(const float2*)(resid + (long)r0*ldc + c0);
                float2 rb = *(const float2*)(resid + (long)(r0+8)*ldc + c0);
                v00+=ra.x; v01+=ra.y; v10+=rb.x; v11+=rb.y;
            }
            if (OUT_HALF){
                __half* C = (__half*)Cv;
                *(__half2*)(C + (long)r0*ldc + c0)     = __floats2half2_rn(v00, v01);
                *(__half2*)(C + (long)(r0+8)*ldc + c0) = __floats2half2_rn(v10, v11);
            } else {
                float* C = (float*)Cv;
                *(float2*)(C + (long)r0*ldc + c0)     = make_float2(v00, v01);
                *(float2*)(C + (long)(r0+8)*ldc + c0) = make_float2(v10, v11);
            }
        }
    }
}

// ---------------------------------------------------------------------------
// Fused flash attention, fp16 operands (Q,K,V,P), fp32 softmax/accumulators.
// Per CTA: 128 Q rows of one (b,h). K,V double-buffered (stride 72 halfs).
// ldmatrix for K (non-trans), P (non-trans A), V (.trans B). 1/8 scale folded
// into the mask multiplier. One __syncthreads per KV tile.
// ---------------------------------------------------------------------------
#define FB_KSZ  18432                  // bytes per K/V buffer (128*72*2)
#define FB_K    0
#define FB_V    (2*FB_KSZ)             // 36864
#define FB_P    (FB_V + 2*FB_KSZ)      // 73728 ; P = 128*136*2 = 34816 B
#define FB_MUL  (FB_P + 34816)         // 108544 ; 2*128 floats = 1024 B
#define FB_ADD  (FB_MUL + 1024)        // 109568
#define FA_SMEM (FB_ADD + 1024)        // 110592 B

__global__ __launch_bounds__(256, 1) void flash_kernel(
    const __half* __restrict__ QKV, const int* __restrict__ mask,
    __half* __restrict__ O)
{
    extern __shared__ char smc[];
    float* fmul = (float*)(smc + FB_MUL);
    float* fadd = (float*)(smc + FB_ADD);
    uint32_t sb = (uint32_t)__cvta_generic_to_shared(smc);

    const int tid = threadIdx.x, lane = tid & 31, w = tid >> 5;
    const int g = lane >> 2, tg = lane & 3, lq = lane & 7, lg = lane >> 3;
    const int bh = blockIdx.y, b = bh >> 4, h = bh & 15;
    const int hcol = h * DK_;
    const int qbase = blockIdx.x * 128;
    const long rowB = (long)b * S_;

    // ---- Q fragments from gmem fp16 (unscaled; 1/8 folded into mask) ----
    uint32_t qa[4][4];
    {
        const __half* q0 = QKV + (rowB + qbase + w*16 + g)*(long)D3_ + hcol;
        const __half* q8 = q0 + 8*(long)D3_;
        #pragma unroll
        for (int ks=0; ks<4; ks++){
            qa[ks][0] = *(const uint32_t*)(q0 + ks*16 + 2*tg);
            qa[ks][1] = *(const uint32_t*)(q8 + ks*16 + 2*tg);
            qa[ks][2] = *(const uint32_t*)(q0 + ks*16 + 2*tg + 8);
            qa[ks][3] = *(const uint32_t*)(q8 + ks*16 + 2*tg + 8);
        }
    }

    // ---- prologue: mask buf0 + K0,V0 ----
    if (tid < 128){
        int mv = mask[rowB + tid];
        fmul[tid] = mv ? 0.125f : 0.f;
        fadd[tid] = mv ? 0.f : -1e9f;
    }
    {
        const __half* Kg = QKV + rowB*D3_ + D_   + hcol;
        const __half* Vg = QKV + rowB*D3_ + 2*D_ + hcol;
        #pragma unroll
        for (int i=0;i<4;i++){
            int idx = i*256 + tid, r = idx >> 3, c = idx & 7;
            cpa16(sb + FB_K + r*144 + c*16, Kg + (long)r*D3_ + c*8);
        }
        #pragma unroll
        for (int i=0;i<4;i++){
            int idx = i*256 + tid, r = idx >> 3, c = idx & 7;
            cpa16(sb + FB_V + r*144 + c*16, Vg + (long)r*D3_ + c*8);
        }
        cpcommit();
    }

    float o_acc[8][4];
    #pragma unroll
    for (int j=0;j<8;j++){ o_acc[j][0]=0.f;o_acc[j][1]=0.f;o_acc[j][2]=0.f;o_acc[j][3]=0.f; }
    float m0 = -__int_as_float(0x7f800000), m1 = m0;
    float l0 = 0.f, l1 = 0.f;

    const int NT = S_ / 128;   // 16
    for (int it = 0; it < NT; it++){
        const int mb = it & 1;
        cpwait0();
        __syncthreads();

        if (it+1 < NT){
            const int nb = (it+1) & 1;
            const __half* Kg = QKV + (rowB + (it+1)*128)*(long)D3_ + D_   + hcol;
            const __half* Vg = QKV + (rowB + (it+1)*128)*(long)D3_ + 2*D_ + hcol;
            #pragma unroll
            for (int i=0;i<4;i++){
                int idx = i*256 + tid, r = idx >> 3, c = idx & 7;
                cpa16(sb + FB_K + nb*FB_KSZ + r*144 + c*16, Kg + (long)r*D3_ + c*8);
            }
            #pragma unroll
            for (int i=0;i<4;i++){
                int idx = i*256 + tid, r = idx >> 3, c = idx & 7;
                cpa16(sb + FB_V + nb*FB_KSZ + r*144 + c*16, Vg + (long)r*D3_ + c*8);
            }
            cpcommit();
            if (tid < 128){
                int mv = mask[rowB + (it+1)*128 + tid];
                fmul[nb*128 + tid] = mv ? 0.125f : 0.f;
                fadd[nb*128 + tid] = mv ? 0.f : -1e9f;
            }
        }

        // ---- scores: S = Q K^T ----
        float c[16][4];
        #pragma unroll
        for (int j=0;j<16;j++){ c[j][0]=0.f;c[j][1]=0.f;c[j][2]=0.f;c[j][3]=0.f; }
        {
            uint32_t kb_base = sb + FB_K + mb*FB_KSZ;
            #pragma unroll
            for (int ks=0; ks<4; ks++){
                #pragma unroll
                for (int jp=0;jp<8;jp++){
                    uint32_t b4[4];
                    int row = jp*16 + (lg>>1)*8 + lq;
                    int col = ks*16 + (lg&1)*8;
                    ldsm4(b4, kb_base + (uint32_t)(row*72 + col)*2);
                    mma16(c[2*jp],   qa[ks], &b4[0]);
                    mma16(c[2*jp+1], qa[ks], &b4[2]);
                }
            }
        }

        // ---- scale+mask + online softmax (fp32) ----
        const float* Mu = fmul + mb*128;
        const float* Ad = fadd + mb*128;
        float mx0 = -3.0e38f, mx1 = -3.0e38f;
        #pragma unroll
        for (int j=0;j<16;j++){
            int cc = j*8 + 2*tg;
            float mu0 = Mu[cc], mu1 = Mu[cc+1];
            float ad0 = Ad[cc], ad1 = Ad[cc+1];
            c[j][0] = fmaf(c[j][0], mu0, ad0);
            c[j][1] = fmaf(c[j][1], mu1, ad1);
            c[j][2] = fmaf(c[j][2], mu0, ad0);
            c[j][3] = fmaf(c[j][3], mu1, ad1);
            mx0 = fmaxf(mx0, fmaxf(c[j][0], c[j][1]));
            mx1 = fmaxf(mx1, fmaxf(c[j][2], c[j][3]));
        }
        mx0 = fmaxf(mx0, __shfl_xor_sync(0xffffffffu, mx0, 1));
        mx0 = fmaxf(mx0, __shfl_xor_sync(0xffffffffu, mx0, 2));
        mx1 = fmaxf(mx1, __shfl_xor_sync(0xffffffffu, mx1, 1));
        mx1 = fmaxf(mx1, __shfl_xor_sync(0xffffffffu, mx1, 2));

        float nm0 = fmaxf(m0, mx0), nm1 = fmaxf(m1, mx1);
        float cr0 = __expf(m0 - nm0), cr1 = __expf(m1 - nm1);
        float s0 = 0.f, s1 = 0.f;
        #pragma unroll
        for (int j=0;j<16;j++){
            c[j][0] = __expf(c[j][0] - nm0);
            c[j][1] = __expf(c[j][1] - nm0);
            c[j][2] = __expf(c[j][2] - nm1);
            c[j][3] = __expf(c[j][3] - nm1);
            s0 += c[j][0] + c[j][1];
            s1 += c[j][2] + c[j][3];
        }
        s0 += __shfl_xor_sync(0xffffffffu, s0, 1);
        s0 += __shfl_xor_sync(0xffffffffu, s0, 2);
        s1 += __shfl_xor_sync(0xffffffffu, s1, 1);
        s1 += __shfl_xor_sync(0xffffffffu, s1, 2);
        l0 = l0*cr0 + s0;  l1 = l1*cr1 + s1;
        m0 = nm0;          m1 = nm1;
        #pragma unroll
        for (int j=0;j<8;j++){
            o_acc[j][0]*=cr0; o_acc[j][1]*=cr0; o_acc[j][2]*=cr1; o_acc[j][3]*=cr1;
        }

        // ---- P (fp16) to smem, warp-private rows ----
        {
            char* Pr0 = smc + FB_P + ((w*16+g)*136 + 2*tg)*2;
            char* Pr8 = Pr0 + 8*136*2;
            #pragma unroll
            for (int j=0;j<16;j++){
                *(__half2*)(Pr0 + j*16) = __floats2half2_rn(c[j][0], c[j][1]);
                *(__half2*)(Pr8 + j*16) = __floats2half2_rn(c[j][2], c[j][3]);
            }
        }
        __syncwarp();

        // ---- O += P @ V : P via ldmatrix (A), V via ldmatrix.trans (B) ----
        {
            uint32_t p_base = sb + FB_P;
            uint32_t v_base = sb + FB_V + mb*FB_KSZ;
            #pragma unroll
            for (int kbi=0; kbi<8; kbi++){
                uint32_t a4[4];
                {
                    int row = w*16 + (lg&1)*8 + lq;
                    int col = kbi*16 + (lg>>1)*8;
                    ldsm4(a4, p_base + (uint32_t)(row*136 + col)*2);
                }
                #pragma unroll
                for (int jo=0; jo<8; jo+=2){
                    uint32_t b4[4];
                    int row = kbi*16 + (lg&1)*8 + lq;       // kv
                    int col = (jo + (lg>>1))*8;             // dk
                    ldsm4t(b4, v_base + (uint32_t)(row*72 + col)*2);
                    mma16(o_acc[jo],   a4, &b4[0]);
                    mma16(o_acc[jo+1], a4, &b4[2]);
                }
            }
        }
    }

    // ---- epilogue: O / l, fp16 output ----
    float inv0 = 1.f / l0, inv1 = 1.f / l1;
    __half* o0 = O + (rowB + qbase + w*16 + g)*(long)D_ + hcol + 2*tg;
    __half* o8 = o0 + 8*(long)D_;
    #pragma unroll
    for (int jo=0; jo<8; jo++){
        *(__half2*)(o0 + jo*8) = __floats2half2_rn(o_acc[jo][0]*inv0, o_acc[jo][1]*inv0);
        *(__half2*)(o8 + jo*8) = __floats2half2_rn(o_acc[jo][2]*inv1, o_acc[jo][3]*inv1);
    }
}

// ---------------------------------------------------------------------------
// Launch
// ---------------------------------------------------------------------------
extern "C" void kernel_launch(void* const* d_in, const int* in_sizes, int n_in,
                              void* d_out, int out_size)
{
    const float* x    = (const float*)d_in[0];
    const int*   mask = (const int*)  d_in[1];
    const float* wq = (const float*)d_in[2];  const float* bq = (const float*)d_in[3];
    const float* wk = (const float*)d_in[4];  const float* bk = (const float*)d_in[5];
    const float* wv = (const float*)d_in[6];  const float* bv = (const float*)d_in[7];
    const float* wo = (const float*)d_in[8];  const float* bo = (const float*)d_in[9];
    const float* w1 = (const float*)d_in[10]; const float* b1 = (const float*)d_in[11];
    const float* w2 = (const float*)d_in[12]; const float* b2 = (const float*)d_in[13];
    const float* a1 = (const float*)d_in[14]; const float* c1 = (const float*)d_in[15];
    const float* a2 = (const float*)d_in[16]; const float* c2 = (const float*)d_in[17];
    float* out = (float*)d_out;

    void* p;
    __half *xnh,*qkvh,*aoh,*hnh,*f1h,*wqkvh,*woh,*w1h,*w2h;
    float *hb,*bqkvb;
    cudaGetSymbolAddress(&p, g_xnh);   xnh   = (__half*)p;
    cudaGetSymbolAddress(&p, g_qkvh);  qkvh  = (__half*)p;
    cudaGetSymbolAddress(&p, g_aoh);   aoh   = (__half*)p;
    cudaGetSymbolAddress(&p, g_hnh);   hnh   = (__half*)p;
    cudaGetSymbolAddress(&p, g_f1h);   f1h   = (__half*)p;
    cudaGetSymbolAddress(&p, g_wqkvh); wqkvh = (__half*)p;
    cudaGetSymbolAddress(&p, g_woh);   woh   = (__half*)p;
    cudaGetSymbolAddress(&p, g_w1h);   w1h   = (__half*)p;
    cudaGetSymbolAddress(&p, g_w2h);   w2h   = (__half*)p;
    cudaGetSymbolAddress(&p, g_h);     hb    = (float*)p;
    cudaGetSymbolAddress(&p, g_bqkv);  bqkvb = (float*)p;

    constexpr int SMEM_G = 3*(128+256)*72*2;   // 165888 B
    cudaFuncSetAttribute((const void*)gemm_h<128,256,true,false,false,true >,
                         cudaFuncAttributeMaxDynamicSharedMemorySize, SMEM_G);
    cudaFuncSetAttribute((const void*)gemm_h<128,256,true,false,true ,false>,
                         cudaFuncAttributeMaxDynamicSharedMemorySize, SMEM_G);
    cudaFuncSetAttribute((const void*)gemm_h<128,256,true,true ,false,true >,
                         cudaFuncAttributeMaxDynamicSharedMemorySize, SMEM_G);
    cudaFuncSetAttribute((const void*)flash_kernel,
                         cudaFuncAttributeMaxDynamicSharedMemorySize, FA_SMEM);

    // 0) weight conversions (fp32 -> fp16) + bias concat
    const long n4dd = (long)D_*D_/4, n4f = (long)DFF_*D_/4;
    f2h_kernel<<<(unsigned)((n4dd+255)/256),256>>>(wq, wqkvh,            n4dd);
    f2h_kernel<<<(unsigned)((n4dd+255)/256),256>>>(wk, wqkvh + D_*D_,    n4dd);
    f2h_kernel<<<(unsigned)((n4dd+255)/256),256>>>(wv, wqkvh + 2*D_*D_,  n4dd);
    f2h_kernel<<<(unsigned)((n4dd+255)/256),256>>>(wo, woh,              n4dd);
    f2h_kernel<<<(unsigned)((n4f +255)/256),256>>>(w1, w1h,              n4f);
    f2h_kernel<<<(unsigned)((n4f +255)/256),256>>>(w2, w2h,              n4f);
    bcat_kernel<<<D3_/256,256>>>(bq, bk, bv, bqkvb);

    // 1) LN1 -> fp16
    ln_kernel<<<M_, 256>>>(x, a1, c1, xnh);

    // 2) fused QKV projection [8192,1024] @ [3072,1024]^T -> fp16
    gemm_h<128,256,true,false,false,true><<<dim3(D3_/256, M_/128), 256, SMEM_G>>>(
        xnh, D_, wqkvh, D_, qkvh, D3_, bqkvb, nullptr, D_);

    // 3) fused flash attention -> fp16 ao
    flash_kernel<<<dim3(S_/128, B_*H_), 256, FA_SMEM>>>(qkvh, mask, aoh);

    // 4) O projection + residual x -> fp32 h
    gemm_h<128,256,true,false,true,false><<<dim3(D_/256, M_/128), 256, SMEM_G>>>(
        aoh, D_, woh, D_, hb, D_, bo, x, D_);

    // 5) LN2 -> fp16
    ln_kernel<<<M_, 256>>>(hb, a2, c2, hnh);

    // 6) FFN1 + ReLU -> fp16
    gemm_h<128,256,true,true,false,true><<<dim3(DFF_/256, M_/128), 256, SMEM_G>>>(
        hnh, D_, w1h, D_, f1h, DFF_, b1, nullptr, D_);

    // 7) FFN2 + residual h -> fp32 out
    gemm_h<128,256,true,false,true,false><<<dim3(D_/256, M_/128), 256, SMEM_G>>>(
        f1h, DFF_, w2h, DFF_, out, D_, b2, hb, DFF_);
}

// round 10
// speedup vs baseline: 2.1489x; 1.0056x over previous
#include <cuda_runtime.h>
#include <cuda_fp16.h>
#include <cstdint>

// Problem constants
#define B_    4
#define S_    2048
#define D_    1024
#define H_    16
#define DK_   64
#define DFF_  4096
#define M_    (B_*S_)   // 8192 rows
#define D3_   (3*D_)    // 3072

// ---------------------------------------------------------------------------
// Static device scratch (allocation-free rule)
// ---------------------------------------------------------------------------
__device__ __half g_xnh [M_*D_];
__device__ __half g_qkvh[M_*D3_];
__device__ __half g_aoh [M_*D_];
__device__ __half g_hnh [M_*D_];
__device__ __half g_f1h [M_*DFF_];
__device__ __half g_wqkvh[D3_*D_];
__device__ __half g_woh [D_*D_];
__device__ __half g_w1h [DFF_*D_];
__device__ __half g_w2h [D_*DFF_];
__device__ float  g_h   [M_*D_];
__device__ float  g_bqkv[D3_];

// ---------------------------------------------------------------------------
// Helpers
// ---------------------------------------------------------------------------
__device__ __forceinline__ float warpRedSum(float v){
    #pragma unroll
    for (int o=16;o;o>>=1) v += __shfl_xor_sync(0xffffffffu, v, o);
    return v;
}
__device__ __forceinline__ void mma16(float c[4], const uint32_t a[4], const uint32_t b[2]){
    asm volatile(
        "mma.sync.aligned.m16n8k16.row.col.f32.f16.f16.f32 "
        "{%0,%1,%2,%3}, {%4,%5,%6,%7}, {%8,%9}, {%0,%1,%2,%3};\n"
        : "+f"(c[0]), "+f"(c[1]), "+f"(c[2]), "+f"(c[3])
        : "r"(a[0]), "r"(a[1]), "r"(a[2]), "r"(a[3]),
          "r"(b[0]), "r"(b[1]));
}
__device__ __forceinline__ void ldsm4(uint32_t r[4], uint32_t a){
    asm volatile("ldmatrix.sync.aligned.m8n8.x4.shared.b16 {%0,%1,%2,%3}, [%4];"
        : "=r"(r[0]), "=r"(r[1]), "=r"(r[2]), "=r"(r[3]) : "r"(a));
}
__device__ __forceinline__ void ldsm4t(uint32_t r[4], uint32_t a){
    asm volatile("ldmatrix.sync.aligned.m8n8.x4.trans.shared.b16 {%0,%1,%2,%3}, [%4];"
        : "=r"(r[0]), "=r"(r[1]), "=r"(r[2]), "=r"(r[3]) : "r"(a));
}
__device__ __forceinline__ void cpa16(uint32_t dst, const void* src){
    asm volatile("cp.async.cg.shared.global [%0], [%1], 16;\n" :: "r"(dst), "l"(src));
}
__device__ __forceinline__ void cpcommit(){ asm volatile("cp.async.commit_group;\n"); }
__device__ __forceinline__ void cpwait0(){ asm volatile("cp.async.wait_group 0;\n"); }
__device__ __forceinline__ void cpwait2(){ asm volatile("cp.async.wait_group 2;\n"); }

// ---------------------------------------------------------------------------
// All weight fp32->fp16 conversions in ONE kernel (grid-stride, 2 float4/iter)
// Segments (float4 units): [0,3n) qkv  [3n,4n) wo  [4n,4n+f) w1  [4n+f,4n+2f) w2
// ---------------------------------------------------------------------------
#define N4DD (D_*D_/4)
#define N4F  (DFF_*D_/4)
#define N4TOT (4*N4DD + 2*N4F)

__global__ void f2h_all(const float* __restrict__ wq, const float* __restrict__ wk,
                        const float* __restrict__ wv, const float* __restrict__ wo,
                        const float* __restrict__ w1, const float* __restrict__ w2,
                        __half* __restrict__ wqkvh, __half* __restrict__ woh,
                        __half* __restrict__ w1h,  __half* __restrict__ w2h)
{
    const long stride = (long)gridDim.x*256;
    for (long i = (long)blockIdx.x*256 + threadIdx.x; i < N4TOT; i += stride){
        const float* src; __half* dst; long off;
        if (i < 3L*N4DD){
            off = i;
            src = (i < N4DD) ? wq : (i < 2L*N4DD) ? wk : wv;
            dst = wqkvh;
            long so = (i < N4DD) ? 0 : (i < 2L*N4DD) ? N4DD : 2L*N4DD;
            float4 v = ((const float4*)src)[i - so];
            __half2 h0 = __floats2half2_rn(v.x, v.y);
            __half2 h1 = __floats2half2_rn(v.z, v.w);
            uint2 u; u.x = *(uint32_t*)&h0; u.y = *(uint32_t*)&h1;
            ((uint2*)dst)[off] = u;
            continue;
        }
        long j = i - 3L*N4DD;
        if (j < N4DD){ src = wo; dst = woh; off = j; }
        else if (j < N4DD + N4F){ src = w1; dst = w1h; off = j - N4DD; }
        else { src = w2; dst = w2h; off = j - N4DD - N4F; }
        float4 v = ((const float4*)src)[off];
        __half2 h0 = __floats2half2_rn(v.x, v.y);
        __half2 h1 = __floats2half2_rn(v.z, v.w);
        uint2 u; u.x = *(uint32_t*)&h0; u.y = *(uint32_t*)&h1;
        ((uint2*)dst)[off] = u;
    }
}
__global__ void bcat_kernel(const float* __restrict__ a, const float* __restrict__ b,
                            const float* __restrict__ c, float* __restrict__ dst)
{
    int t = blockIdx.x*256 + threadIdx.x;
    dst[t] = (t < D_) ? a[t] : (t < 2*D_) ? b[t-D_] : c[t-2*D_];
}

// ---------------------------------------------------------------------------
// LayerNorm (torch-style), fp16 output
// ---------------------------------------------------------------------------
__global__ void ln_kernel(const float* __restrict__ x,
                          const float* __restrict__ alpha,
                          const float* __restrict__ beta,
                          __half* __restrict__ y)
{
    __shared__ float s1[8], s2[8];
    long row = blockIdx.x;
    const float4* xr = (const float4*)(x + row*(long)D_);
    float4 v = xr[threadIdx.x];
    float sum = v.x+v.y+v.z+v.w;
    float sq  = v.x*v.x+v.y*v.y+v.z*v.z+v.w*v.w;
    int lane = threadIdx.x & 31, w = threadIdx.x >> 5;
    sum = warpRedSum(sum); sq = warpRedSum(sq);
    if (lane==0){ s1[w]=sum; s2[w]=sq; }
    __syncthreads();
    if (w==0){
        float a = (lane<8)? s1[lane] : 0.f;
        float b = (lane<8)? s2[lane] : 0.f;
        a = warpRedSum(a); b = warpRedSum(b);
        if (lane==0){ s1[0]=a; s2[0]=b; }
    }
    __syncthreads();
    float mean = s1[0] * (1.f/D_);
    float var  = (s2[0] - (float)D_*mean*mean) * (1.f/(D_-1));
    var = fmaxf(var, 0.f);
    float inv = alpha[0] / (sqrtf(var) + 1e-6f);
    float c   = beta[0];
    __half2 h0 = __floats2half2_rn((v.x-mean)*inv+c, (v.y-mean)*inv+c);
    __half2 h1 = __floats2half2_rn((v.z-mean)*inv+c, (v.w-mean)*inv+c);
    uint2 u; u.x = *(uint32_t*)&h0; u.y = *(uint32_t*)&h1;
    ((uint2*)(y + row*(long)D_))[threadIdx.x] = u;
}

// ---------------------------------------------------------------------------
// fp16 NT GEMM (m16n8k16), ldmatrix fragments, 4-stage cp.async ring (BK=64):
//   C[m,n] = sum_k A[m,k]*B[n,k] (+bias[n]) (+relu) (+resid[m,n])
// ---------------------------------------------------------------------------
template<int BM,int BN,bool HAS_BIAS,bool RELU,bool HAS_RESID,bool OUT_HALF>
__global__ __launch_bounds__(256) void gemm_h(
    const __half* __restrict__ A, int lda,
    const __half* __restrict__ Bm, int ldb,
    void* __restrict__ Cv, int ldc,
    const float* __restrict__ bias, const float* __restrict__ resid,
    int K)
{
    constexpr int AW = 72;                     // halfs per smem row
    constexpr int STAGE_B = (BM+BN)*AW*2;      // bytes per stage

    extern __shared__ char smc[];
    uint32_t sb = (uint32_t)__cvta_generic_to_shared(smc);

    const int tid = threadIdx.x, lane = tid & 31, warp = tid >> 5;
    const int g = lane >> 2, tg = lane & 3, lq = lane & 7, lg = lane >> 3;
    const int wm = warp >> 2, wn = warp & 3;        // 2 x 4 warps
    const int m0 = blockIdx.y*BM, n0 = blockIdx.x*BN;

    float acc[4][8][4];
    #pragma unroll
    for (int i=0;i<4;i++)
        #pragma unroll
        for (int j=0;j<8;j++)
            #pragma unroll
            for (int r=0;r<4;r++) acc[i][j][r]=0.f;

    auto loadt = [&](int k0, int s){
        uint32_t st = sb + s*STAGE_B;
        #pragma unroll
        for (int i=0;i<BM*8;i+=256){
            int idx=i+tid, r=idx>>3, c=idx&7;
            cpa16(st + r*144 + c*16, A + (long)(m0+r)*lda + k0 + c*8);
        }
        uint32_t stB = st + BM*144;
        #pragma unroll
        for (int i=0;i<BN*8;i+=256){
            int idx=i+tid, r=idx>>3, c=idx&7;
            cpa16(stB + r*144 + c*16, Bm + (long)(n0+r)*ldb + k0 + c*8);
        }
        cpcommit();
    };

    const int nt = K/64;                        // >= 16 at all call sites
    loadt(0,0); loadt(64,1); loadt(128,2);

    for (int ch=0; ch<nt; ch++){
        int s = ch & 3;
        cpwait2();                // chunk ch's group complete (2 in flight)
        __syncthreads();          // all warps past stage (ch-1)&3
        if (ch+3<nt) loadt((ch+3)*64, (ch+3)&3);
        else cpcommit();          // keep group accounting aligned

        uint32_t sA = sb + s*STAGE_B;
        uint32_t sB = sA + BM*144;

        #pragma unroll
        for (int kb=0; kb<64; kb+=16){
            uint32_t a4[4][4], b4[4][4];
            #pragma unroll
            for (int im=0;im<4;im++){
                int row = wm*64 + im*16 + (lg&1)*8 + lq;
                int col = kb + (lg>>1)*8;
                ldsm4(a4[im], sA + (uint32_t)(row*AW + col)*2);
            }
            #pragma unroll
            for (int jp=0;jp<4;jp++){
                int row = wn*64 + jp*16 + (lg>>1)*8 + lq;
                int col = kb + (lg&1)*8;
                ldsm4(b4[jp], sB + (uint32_t)(row*AW + col)*2);
            }
            #pragma unroll
            for (int im=0;im<4;im++)
                #pragma unroll
                for (int jp=0;jp<4;jp++){
                    mma16(acc[im][2*jp],   a4[im], &b4[jp][0]);
                    mma16(acc[im][2*jp+1], a4[im], &b4[jp][2]);
                }
        }
    }

    // epilogue
    #pragma unroll
    for (int im=0;im<4;im++){
        int r0 = m0 + wm*64 + im*16 + g;
        #pragma unroll
        for (int jn=0;jn<8;jn++){
            int c0 = n0 + wn*64 + jn*8 + tg*2;
            float2 bv = HAS_BIAS ? *(const float2*)(bias + c0) : make_float2(0.f,0.f);
            float v00 = acc[im][jn][0] + bv.x;
            float v01 = acc[im][jn][1] + bv.y;
            float v10 = acc[im][jn][2] + bv.x;
            float v11 = acc[im][jn][3] + bv.y;
            if (RELU){
                v00=fmaxf(v00,0.f); v01=fmaxf(v01,0.f);
                v10=fmaxf(v10,0.f); v11=fmaxf(v11,0.f);
            }
            if (HAS_RESID){
                float2 ra = *(const float2*)(resid + (long)r0*ldc + c0);
                float2 rb = *(const float2*)(resid + (long)(r0+8)*ldc + c0);
                v00+=ra.x; v01+=ra.y; v10+=rb.x; v11+=rb.y;
            }
            if (OUT_HALF){
                __half* C = (__half*)Cv;
                *(__half2*)(C + (long)r0*ldc + c0)     = __floats2half2_rn(v00, v01);
                *(__half2*)(C + (long)(r0+8)*ldc + c0) = __floats2half2_rn(v10, v11);
            } else {
                float* C = (float*)Cv;
                *(float2*)(C + (long)r0*ldc + c0)     = make_float2(v00, v01);
                *(float2*)(C + (long)(r0+8)*ldc + c0) = make_float2(v10, v11);
            }
        }
    }
}

// ---------------------------------------------------------------------------
// Fused flash attention, fp16 operands, fp32 softmax (log2 domain / exp2f).
// 2 CTAs/SM (reg cap 128 — qa may spill, reloaded from L1 per tile).
// ---------------------------------------------------------------------------
#define FB_KSZ  18432                  // bytes per K/V buffer (128*72*2)
#define FB_K    0
#define FB_V    (2*FB_KSZ)             // 36864
#define FB_P    (FB_V + 2*FB_KSZ)      // 73728 ; P = 128*136*2 = 34816 B
#define FB_MUL  (FB_P + 34816)         // 108544 ; 2*128 floats
#define FB_ADD  (FB_MUL + 1024)        // 109568
#define FA_SMEM (FB_ADD + 1024)        // 110592 B  (x2 CTAs = 221184 <= 227KB)

#define LOG2E 1.4426950408889634f

__global__ __launch_bounds__(256, 2) void flash_kernel(
    const __half* __restrict__ QKV, const int* __restrict__ mask,
    __half* __restrict__ O)
{
    extern __shared__ char smc[];
    float* fmul = (float*)(smc + FB_MUL);
    float* fadd = (float*)(smc + FB_ADD);
    uint32_t sb = (uint32_t)__cvta_generic_to_shared(smc);

    const int tid = threadIdx.x, lane = tid & 31, w = tid >> 5;
    const int g = lane >> 2, tg = lane & 3, lq = lane & 7, lg = lane >> 3;
    const int bh = blockIdx.y, b = bh >> 4, h = bh & 15;
    const int hcol = h * DK_;
    const int qbase = blockIdx.x * 128;
    const long rowB = (long)b * S_;

    // ---- Q fragments (unscaled; scale*log2e folded into mask mult) ----
    uint32_t qa[4][4];
    {
        const __half* q0 = QKV + (rowB + qbase + w*16 + g)*(long)D3_ + hcol;
        const __half* q8 = q0 + 8*(long)D3_;
        #pragma unroll
        for (int ks=0; ks<4; ks++){
            qa[ks][0] = *(const uint32_t*)(q0 + ks*16 + 2*tg);
            qa[ks][1] = *(const uint32_t*)(q8 + ks*16 + 2*tg);
            qa[ks][2] = *(const uint32_t*)(q0 + ks*16 + 2*tg + 8);
            qa[ks][3] = *(const uint32_t*)(q8 + ks*16 + 2*tg + 8);
        }
    }

    // ---- prologue: mask buf0 + K0,V0 ----
    if (tid < 128){
        int mv = mask[rowB + tid];
        fmul[tid] = mv ? 0.125f*LOG2E : 0.f;
        fadd[tid] = mv ? 0.f : -1e9f*LOG2E;
    }
    {
        const __half* Kg = QKV + rowB*D3_ + D_   + hcol;
        const __half* Vg = QKV + rowB*D3_ + 2*D_ + hcol;
        #pragma unroll
        for (int i=0;i<4;i++){
            int idx = i*256 + tid, r = idx >> 3, c = idx & 7;
            cpa16(sb + FB_K + r*144 + c*16, Kg + (long)r*D3_ + c*8);
        }
        #pragma unroll
        for (int i=0;i<4;i++){
            int idx = i*256 + tid, r = idx >> 3, c = idx & 7;
            cpa16(sb + FB_V + r*144 + c*16, Vg + (long)r*D3_ + c*8);
        }
        cpcommit();
    }

    float o_acc[8][4];
    #pragma unroll
    for (int j=0;j<8;j++){ o_acc[j][0]=0.f;o_acc[j][1]=0.f;o_acc[j][2]=0.f;o_acc[j][3]=0.f; }
    float m0 = -__int_as_float(0x7f800000), m1 = m0;   // running max (log2 dom)
    float l0 = 0.f, l1 = 0.f;

    const int NT = S_ / 128;   // 16
    for (int it = 0; it < NT; it++){
        const int mb = it & 1;
        cpwait0();
        __syncthreads();

        if (it+1 < NT){
            const int nb = (it+1) & 1;
            const __half* Kg = QKV + (rowB + (it+1)*128)*(long)D3_ + D_   + hcol;
            const __half* Vg = QKV + (rowB + (it+1)*128)*(long)D3_ + 2*D_ + hcol;
            #pragma unroll
            for (int i=0;i<4;i++){
                int idx = i*256 + tid, r = idx >> 3, c = idx & 7;
                cpa16(sb + FB_K + nb*FB_KSZ + r*144 + c*16, Kg + (long)r*D3_ + c*8);
            }
            #pragma unroll
            for (int i=0;i<4;i++){
                int idx = i*256 + tid, r = idx >> 3, c = idx & 7;
                cpa16(sb + FB_V + nb*FB_KSZ + r*144 + c*16, Vg + (long)r*D3_ + c*8);
            }
            cpcommit();
            if (tid < 128){
                int mv = mask[rowB + (it+1)*128 + tid];
                fmul[nb*128 + tid] = mv ? 0.125f*LOG2E : 0.f;
                fadd[nb*128 + tid] = mv ? 0.f : -1e9f*LOG2E;
            }
        }

        // ---- scores: S = Q K^T ----
        float c[16][4];
        #pragma unroll
        for (int j=0;j<16;j++){ c[j][0]=0.f;c[j][1]=0.f;c[j][2]=0.f;c[j][3]=0.f; }
        {
            uint32_t kb_base = sb + FB_K + mb*FB_KSZ;
            #pragma unroll
            for (int ks=0; ks<4; ks++){
                #pragma unroll
                for (int jp=0;jp<8;jp++){
                    uint32_t b4[4];
                    int row = jp*16 + (lg>>1)*8 + lq;
                    int col = ks*16 + (lg&1)*8;
                    ldsm4(b4, kb_base + (uint32_t)(row*72 + col)*2);
                    mma16(c[2*jp],   qa[ks], &b4[0]);
                    mma16(c[2*jp+1], qa[ks], &b4[2]);
                }
            }
        }

        // ---- scale+mask (log2 domain) + online softmax via exp2 ----
        const float* Mu = fmul + mb*128;
        const float* Ad = fadd + mb*128;
        float mx0 = -3.0e38f, mx1 = -3.0e38f;
        #pragma unroll
        for (int j=0;j<16;j++){
            int cc = j*8 + 2*tg;
            float mu0 = Mu[cc], mu1 = Mu[cc+1];
            float ad0 = Ad[cc], ad1 = Ad[cc+1];
            c[j][0] = fmaf(c[j][0], mu0, ad0);
            c[j][1] = fmaf(c[j][1], mu1, ad1);
            c[j][2] = fmaf(c[j][2], mu0, ad0);
            c[j][3] = fmaf(c[j][3], mu1, ad1);
            mx0 = fmaxf(mx0, fmaxf(c[j][0], c[j][1]));
            mx1 = fmaxf(mx1, fmaxf(c[j][2], c[j][3]));
        }
        mx0 = fmaxf(mx0, __shfl_xor_sync(0xffffffffu, mx0, 1));
        mx0 = fmaxf(mx0, __shfl_xor_sync(0xffffffffu, mx0, 2));
        mx1 = fmaxf(mx1, __shfl_xor_sync(0xffffffffu, mx1, 1));
        mx1 = fmaxf(mx1, __shfl_xor_sync(0xffffffffu, mx1, 2));

        float nm0 = fmaxf(m0, mx0), nm1 = fmaxf(m1, mx1);
        float cr0 = exp2f(m0 - nm0), cr1 = exp2f(m1 - nm1);
        float s0 = 0.f, s1 = 0.f;
        #pragma unroll
        for (int j=0;j<16;j++){
            c[j][0] = exp2f(c[j][0] - nm0);
            c[j][1] = exp2f(c[j][1] - nm0);
            c[j][2] = exp2f(c[j][2] - nm1);
            c[j][3] = exp2f(c[j][3] - nm1);
            s0 += c[j][0] + c[j][1];
            s1 += c[j][2] + c[j][3];
        }
        s0 += __shfl_xor_sync(0xffffffffu, s0, 1);
        s0 += __shfl_xor_sync(0xffffffffu, s0, 2);
        s1 += __shfl_xor_sync(0xffffffffu, s1, 1);
        s1 += __shfl_xor_sync(0xffffffffu, s1, 2);
        l0 = l0*cr0 + s0;  l1 = l1*cr1 + s1;
        m0 = nm0;          m1 = nm1;
        #pragma unroll
        for (int j=0;j<8;j++){
            o_acc[j][0]*=cr0; o_acc[j][1]*=cr0; o_acc[j][2]*=cr1; o_acc[j][3]*=cr1;
        }

        // ---- P (fp16) to smem, warp-private rows ----
        {
            char* Pr0 = smc + FB_P + ((w*16+g)*136 + 2*tg)*2;
            char* Pr8 = Pr0 + 8*136*2;
            #pragma unroll
            for (int j=0;j<16;j++){
                *(__half2*)(Pr0 + j*16) = __floats2half2_rn(c[j][0], c[j][1]);
                *(__half2*)(Pr8 + j*16) = __floats2half2_rn(c[j][2], c[j][3]);
            }
        }
        __syncwarp();

        // ---- O += P @ V ----
        {
            uint32_t p_base = sb + FB_P;
            uint32_t v_base = sb + FB_V + mb*FB_KSZ;
            #pragma unroll
            for (int kbi=0; kbi<8; kbi++){
                uint32_t a4[4];
                {
                    int row = w*16 + (lg&1)*8 + lq;
                    int col = kbi*16 + (lg>>1)*8;
                    ldsm4(a4, p_base + (uint32_t)(row*136 + col)*2);
                }
                #pragma unroll
                for (int jo=0; jo<8; jo+=2){
                    uint32_t b4[4];
                    int row = kbi*16 + (lg&1)*8 + lq;       // kv
                    int col = (jo + (lg>>1))*8;             // dk
                    ldsm4t(b4, v_base + (uint32_t)(row*72 + col)*2);
                    mma16(o_acc[jo],   a4, &b4[0]);
                    mma16(o_acc[jo+1], a4, &b4[2]);
                }
            }
        }
    }

    // ---- epilogue: O / l, fp16 output ----
    float inv0 = 1.f / l0, inv1 = 1.f / l1;
    __half* o0 = O + (rowB + qbase + w*16 + g)*(long)D_ + hcol + 2*tg;
    __half* o8 = o0 + 8*(long)D_;
    #pragma unroll
    for (int jo=0; jo<8; jo++){
        *(__half2*)(o0 + jo*8) = __floats2half2_rn(o_acc[jo][0]*inv0, o_acc[jo][1]*inv0);
        *(__half2*)(o8 + jo*8) = __floats2half2_rn(o_acc[jo][2]*inv1, o_acc[jo][3]*inv1);
    }
}

// ---------------------------------------------------------------------------
// Launch
// ---------------------------------------------------------------------------
extern "C" void kernel_launch(void* const* d_in, const int* in_sizes, int n_in,
                              void* d_out, int out_size)
{
    const float* x    = (const float*)d_in[0];
    const int*   mask = (const int*)  d_in[1];
    const float* wq = (const float*)d_in[2];  const float* bq = (const float*)d_in[3];
    const float* wk = (const float*)d_in[4];  const float* bk = (const float*)d_in[5];
    const float* wv = (const float*)d_in[6];  const float* bv = (const float*)d_in[7];
    const float* wo = (const float*)d_in[8];  const float* bo = (const float*)d_in[9];
    const float* w1 = (const float*)d_in[10]; const float* b1 = (const float*)d_in[11];
    const float* w2 = (const float*)d_in[12]; const float* b2 = (const float*)d_in[13];
    const float* a1 = (const float*)d_in[14]; const float* c1 = (const float*)d_in[15];
    const float* a2 = (const float*)d_in[16]; const float* c2 = (const float*)d_in[17];
    float* out = (float*)d_out;

    void* p;
    __half *xnh,*qkvh,*aoh,*hnh,*f1h,*wqkvh,*woh,*w1h,*w2h;
    float *hb,*bqkvb;
    cudaGetSymbolAddress(&p, g_xnh);   xnh   = (__half*)p;
    cudaGetSymbolAddress(&p, g_qkvh);  qkvh  = (__half*)p;
    cudaGetSymbolAddress(&p, g_aoh);   aoh   = (__half*)p;
    cudaGetSymbolAddress(&p, g_hnh);   hnh   = (__half*)p;
    cudaGetSymbolAddress(&p, g_f1h);   f1h   = (__half*)p;
    cudaGetSymbolAddress(&p, g_wqkvh); wqkvh = (__half*)p;
    cudaGetSymbolAddress(&p, g_woh);   woh   = (__half*)p;
    cudaGetSymbolAddress(&p, g_w1h);   w1h   = (__half*)p;
    cudaGetSymbolAddress(&p, g_w2h);   w2h   = (__half*)p;
    cudaGetSymbolAddress(&p, g_h);     hb    = (float*)p;
    cudaGetSymbolAddress(&p, g_bqkv);  bqkvb = (float*)p;

    constexpr int SMEM_G = 4*(128+256)*72*2;   // 221184 B
    cudaFuncSetAttribute((const void*)gemm_h<128,256,true,false,false,true >,
                         cudaFuncAttributeMaxDynamicSharedMemorySize, SMEM_G);
    cudaFuncSetAttribute((const void*)gemm_h<128,256,true,false,true ,false>,
                         cudaFuncAttributeMaxDynamicSharedMemorySize, SMEM_G);
    cudaFuncSetAttribute((const void*)gemm_h<128,256,true,true ,false,true >,
                         cudaFuncAttributeMaxDynamicSharedMemorySize, SMEM_G);
    cudaFuncSetAttribute((const void*)flash_kernel,
                         cudaFuncAttributeMaxDynamicSharedMemorySize, FA_SMEM);

    // 0) all weight conversions in one launch + bias concat
    f2h_all<<<1536, 256>>>(wq, wk, wv, wo, w1, w2, wqkvh, woh, w1h, w2h);
    bcat_kernel<<<D3_/256,256>>>(bq, bk, bv, bqkvb);

    // 1) LN1 -> fp16
    ln_kernel<<<M_, 256>>>(x, a1, c1, xnh);

    // 2) fused QKV projection [8192,1024] @ [3072,1024]^T -> fp16
    gemm_h<128,256,true,false,false,true><<<dim3(D3_/256, M_/128), 256, SMEM_G>>>(
        xnh, D_, wqkvh, D_, qkvh, D3_, bqkvb, nullptr, D_);

    // 3) fused flash attention -> fp16 ao
    flash_kernel<<<dim3(S_/128, B_*H_), 256, FA_SMEM>>>(qkvh, mask, aoh);

    // 4) O projection + residual x -> fp32 h
    gemm_h<128,256,true,false,true,false><<<dim3(D_/256, M_/128), 256, SMEM_G>>>(
        aoh, D_, woh, D_, hb, D_, bo, x, D_);

    // 5) LN2 -> fp16
    ln_kernel<<<M_, 256>>>(hb, a2, c2, hnh);

    // 6) FFN1 + ReLU -> fp16
    gemm_h<128,256,true,true,false,true><<<dim3(DFF_/256, M_/128), 256, SMEM_G>>>(
        hnh, D_, w1h, D_, f1h, DFF_, b1, nullptr, D_);

    // 7) FFN2 + residual h -> fp32 out
    gemm_h<128,256,true,false,true,false><<<dim3(D_/256, M_/128), 256, SMEM_G>>>(
        f1h, DFF_, w2h, DFF_, out, D_, b2, hb, DFF_);
}

// round 12
// speedup vs baseline: 2.2803x; 1.0612x over previous
#include <cuda_runtime.h>
#include <cuda_fp16.h>
#include <cstdint>

// Problem constants
#define B_    4
#define S_    2048
#define D_    1024
#define H_    16
#define DK_   64
#define DFF_  4096
#define M_    (B_*S_)   // 8192 rows
#define D3_   (3*D_)    // 3072

// ---------------------------------------------------------------------------
// Static device scratch (allocation-free rule)
// ---------------------------------------------------------------------------
__device__ __half g_xnh [M_*D_];
__device__ __half g_qkvh[M_*D3_];
__device__ __half g_aoh [M_*D_];
__device__ __half g_hnh [M_*D_];
__device__ __half g_f1h [M_*DFF_];
__device__ __half g_wqkvh[D3_*D_];
__device__ __half g_woh [D_*D_];
__device__ __half g_w1h [DFF_*D_];
__device__ __half g_w2h [D_*DFF_];
__device__ float  g_h   [M_*D_];
__device__ float  g_bqkv[D3_];

// ---------------------------------------------------------------------------
// Helpers
// ---------------------------------------------------------------------------
__device__ __forceinline__ float warpRedSum(float v){
    #pragma unroll
    for (int o=16;o;o>>=1) v += __shfl_xor_sync(0xffffffffu, v, o);
    return v;
}
__device__ __forceinline__ void mma16(float c[4], const uint32_t a[4], const uint32_t b[2]){
    asm volatile(
        "mma.sync.aligned.m16n8k16.row.col.f32.f16.f16.f32 "
        "{%0,%1,%2,%3}, {%4,%5,%6,%7}, {%8,%9}, {%0,%1,%2,%3};\n"
        : "+f"(c[0]), "+f"(c[1]), "+f"(c[2]), "+f"(c[3])
        : "r"(a[0]), "r"(a[1]), "r"(a[2]), "r"(a[3]),
          "r"(b[0]), "r"(b[1]));
}
__device__ __forceinline__ void ldsm4(uint32_t r[4], uint32_t a){
    asm volatile("ldmatrix.sync.aligned.m8n8.x4.shared.b16 {%0,%1,%2,%3}, [%4];"
        : "=r"(r[0]), "=r"(r[1]), "=r"(r[2]), "=r"(r[3]) : "r"(a));
}
__device__ __forceinline__ void ldsm4t(uint32_t r[4], uint32_t a){
    asm volatile("ldmatrix.sync.aligned.m8n8.x4.trans.shared.b16 {%0,%1,%2,%3}, [%4];"
        : "=r"(r[0]), "=r"(r[1]), "=r"(r[2]), "=r"(r[3]) : "r"(a));
}
__device__ __forceinline__ void cpa16(uint32_t dst, const void* src){
    asm volatile("cp.async.cg.shared.global [%0], [%1], 16;\n" :: "r"(dst), "l"(src));
}
__device__ __forceinline__ void cpcommit(){ asm volatile("cp.async.commit_group;\n"); }
__device__ __forceinline__ void cpwait0(){ asm volatile("cp.async.wait_group 0;\n"); }
__device__ __forceinline__ void cpwait1(){ asm volatile("cp.async.wait_group 1;\n"); }

// ---------------------------------------------------------------------------
// All weight fp32->fp16 conversions in ONE kernel (grid-stride)
// ---------------------------------------------------------------------------
#define N4DD (D_*D_/4)
#define N4F  (DFF_*D_/4)
#define N4TOT (4*N4DD + 2*N4F)

__global__ void f2h_all(const float* __restrict__ wq, const float* __restrict__ wk,
                        const float* __restrict__ wv, const float* __restrict__ wo,
                        const float* __restrict__ w1, const float* __restrict__ w2,
                        __half* __restrict__ wqkvh, __half* __restrict__ woh,
                        __half* __restrict__ w1h,  __half* __restrict__ w2h)
{
    const long stride = (long)gridDim.x*256;
    for (long i = (long)blockIdx.x*256 + threadIdx.x; i < N4TOT; i += stride){
        const float* src; __half* dst; long off;
        if (i < 3L*N4DD){
            off = i;
            src = (i < N4DD) ? wq : (i < 2L*N4DD) ? wk : wv;
            dst = wqkvh;
            long so = (i < N4DD) ? 0 : (i < 2L*N4DD) ? N4DD : 2L*N4DD;
            float4 v = ((const float4*)src)[i - so];
            __half2 h0 = __floats2half2_rn(v.x, v.y);
            __half2 h1 = __floats2half2_rn(v.z, v.w);
            uint2 u; u.x = *(uint32_t*)&h0; u.y = *(uint32_t*)&h1;
            ((uint2*)dst)[off] = u;
            continue;
        }
        long j = i - 3L*N4DD;
        if (j < N4DD){ src = wo; dst = woh; off = j; }
        else if (j < N4DD + N4F){ src = w1; dst = w1h; off = j - N4DD; }
        else { src = w2; dst = w2h; off = j - N4DD - N4F; }
        float4 v = ((const float4*)src)[off];
        __half2 h0 = __floats2half2_rn(v.x, v.y);
        __half2 h1 = __floats2half2_rn(v.z, v.w);
        uint2 u; u.x = *(uint32_t*)&h0; u.y = *(uint32_t*)&h1;
        ((uint2*)dst)[off] = u;
    }
}
__global__ void bcat_kernel(const float* __restrict__ a, const float* __restrict__ b,
                            const float* __restrict__ c, float* __restrict__ dst)
{
    int t = blockIdx.x*256 + threadIdx.x;
    dst[t] = (t < D_) ? a[t] : (t < 2*D_) ? b[t-D_] : c[t-2*D_];
}

// ---------------------------------------------------------------------------
// LayerNorm (torch-style), fp16 output
// ---------------------------------------------------------------------------
__global__ void ln_kernel(const float* __restrict__ x,
                          const float* __restrict__ alpha,
                          const float* __restrict__ beta,
                          __half* __restrict__ y)
{
    __shared__ float s1[8], s2[8];
    long row = blockIdx.x;
    const float4* xr = (const float4*)(x + row*(long)D_);
    float4 v = xr[threadIdx.x];
    float sum = v.x+v.y+v.z+v.w;
    float sq  = v.x*v.x+v.y*v.y+v.z*v.z+v.w*v.w;
    int lane = threadIdx.x & 31, w = threadIdx.x >> 5;
    sum = warpRedSum(sum); sq = warpRedSum(sq);
    if (lane==0){ s1[w]=sum; s2[w]=sq; }
    __syncthreads();
    if (w==0){
        float a = (lane<8)? s1[lane] : 0.f;
        float b = (lane<8)? s2[lane] : 0.f;
        a = warpRedSum(a); b = warpRedSum(b);
        if (lane==0){ s1[0]=a; s2[0]=b; }
    }
    __syncthreads();
    float mean = s1[0] * (1.f/D_);
    float var  = (s2[0] - (float)D_*mean*mean) * (1.f/(D_-1));
    var = fmaxf(var, 0.f);
    float inv = alpha[0] / (sqrtf(var) + 1e-6f);
    float c   = beta[0];
    __half2 h0 = __floats2half2_rn((v.x-mean)*inv+c, (v.y-mean)*inv+c);
    __half2 h1 = __floats2half2_rn((v.z-mean)*inv+c, (v.w-mean)*inv+c);
    uint2 u; u.x = *(uint32_t*)&h0; u.y = *(uint32_t*)&h1;
    ((uint2*)(y + row*(long)D_))[threadIdx.x] = u;
}

// ---------------------------------------------------------------------------
// fp16 NT GEMM (m16n8k16), 128x128 tile, 3-stage ring, 2 CTAs/SM:
//   C[m,n] = sum_k A[m,k]*B[n,k] (+bias[n]) (+relu) (+resid[m,n])
// Warp tile 64x32 (2x4 warp grid). acc = 64 regs -> fits 128-reg cap.
// ---------------------------------------------------------------------------
template<bool HAS_BIAS,bool RELU,bool HAS_RESID,bool OUT_HALF>
__global__ __launch_bounds__(256, 2) void gemm_h(
    const __half* __restrict__ A, int lda,
    const __half* __restrict__ Bm, int ldb,
    void* __restrict__ Cv, int ldc,
    const float* __restrict__ bias, const float* __restrict__ resid,
    int K)
{
    constexpr int BM = 128, BN = 128;
    constexpr int AW = 72;                     // halfs per smem row
    constexpr int STAGE_B = (BM+BN)*AW*2;      // 36864 bytes per stage

    extern __shared__ char smc[];
    uint32_t sb = (uint32_t)__cvta_generic_to_shared(smc);

    const int tid = threadIdx.x, lane = tid & 31, warp = tid >> 5;
    const int g = lane >> 2, tg = lane & 3, lq = lane & 7, lg = lane >> 3;
    const int wm = warp >> 2, wn = warp & 3;        // 2 x 4 warps
    const int m0 = blockIdx.y*BM, n0 = blockIdx.x*BN;

    float acc[4][4][4];
    #pragma unroll
    for (int i=0;i<4;i++)
        #pragma unroll
        for (int j=0;j<4;j++)
            #pragma unroll
            for (int r=0;r<4;r++) acc[i][j][r]=0.f;

    auto loadt = [&](int k0, int s){
        uint32_t st = sb + s*STAGE_B;
        #pragma unroll
        for (int i=0;i<BM*8;i+=256){
            int idx=i+tid, r=idx>>3, c=idx&7;
            cpa16(st + r*144 + c*16, A + (long)(m0+r)*lda + k0 + c*8);
        }
        uint32_t stB = st + BM*144;
        #pragma unroll
        for (int i=0;i<BN*8;i+=256){
            int idx=i+tid, r=idx>>3, c=idx&7;
            cpa16(stB + r*144 + c*16, Bm + (long)(n0+r)*ldb + k0 + c*8);
        }
        cpcommit();
    };

    const int nt = K/64;
    loadt(0,0); loadt(64,1);

    for (int ch=0; ch<nt; ch++){
        int s = ch%3;
        if (ch+2<nt) cpwait1(); else cpwait0();   // chunk ch arrived
        __syncthreads();                          // all warps done with stage (ch-1)%3
        if (ch+2<nt) loadt((ch+2)*64, (ch+2)%3);  // refill the freed stage

        uint32_t sA = sb + s*STAGE_B;
        uint32_t sB = sA + BM*144;

        #pragma unroll
        for (int kb=0; kb<64; kb+=16){
            uint32_t a4[4][4], b4[2][4];
            #pragma unroll
            for (int im=0;im<4;im++){
                int row = wm*64 + im*16 + (lg&1)*8 + lq;
                int col = kb + (lg>>1)*8;
                ldsm4(a4[im], sA + (uint32_t)(row*AW + col)*2);
            }
            #pragma unroll
            for (int jp=0;jp<2;jp++){
                int row = wn*32 + jp*16 + (lg>>1)*8 + lq;
                int col = kb + (lg&1)*8;
                ldsm4(b4[jp], sB + (uint32_t)(row*AW + col)*2);
            }
            #pragma unroll
            for (int im=0;im<4;im++)
                #pragma unroll
                for (int jp=0;jp<2;jp++){
                    mma16(acc[im][2*jp],   a4[im], &b4[jp][0]);
                    mma16(acc[im][2*jp+1], a4[im], &b4[jp][2]);
                }
        }
    }

    // epilogue
    #pragma unroll
    for (int im=0;im<4;im++){
        int r0 = m0 + wm*64 + im*16 + g;
        #pragma unroll
        for (int jn=0;jn<4;jn++){
            int c0 = n0 + wn*32 + jn*8 + tg*2;
            float2 bv = HAS_BIAS ? *(const float2*)(bias + c0) : make_float2(0.f,0.f);
            float v00 = acc[im][jn][0] + bv.x;
            float v01 = acc[im][jn][1] + bv.y;
            float v10 = acc[im][jn][2] + bv.x;
            float v11 = acc[im][jn][3] + bv.y;
            if (RELU){
                v00=fmaxf(v00,0.f); v01=fmaxf(v01,0.f);
                v10=fmaxf(v10,0.f); v11=fmaxf(v11,0.f);
            }
            if (HAS_RESID){
                float2 ra = *(const float2*)(resid + (long)r0*ldc + c0);
                float2 rb = *(const float2*)(resid + (long)(r0+8)*ldc + c0);
                v00+=ra.x; v01+=ra.y; v10+=rb.x; v11+=rb.y;
            }
            if (OUT_HALF){
                __half* C = (__half*)Cv;
                *(__half2*)(C + (long)r0*ldc + c0)     = __floats2half2_rn(v00, v01);
                *(__half2*)(C + (long)(r0+8)*ldc + c0) = __floats2half2_rn(v10, v11);
            } else {
                float* C = (float*)Cv;
                *(float2*)(C + (long)r0*ldc + c0)     = make_float2(v00, v01);
                *(float2*)(C + (long)(r0+8)*ldc + c0) = make_float2(v10, v11);
            }
        }
    }
}

// ---------------------------------------------------------------------------
// Fused flash attention, fp16 operands, fp32 softmax (log2 domain / exp2f).
// 1 CTA/SM (registers uncapped — no spills in the hot loop).
// ---------------------------------------------------------------------------
#define FB_KSZ  18432                  // bytes per K/V buffer (128*72*2)
#define FB_K    0
#define FB_V    (2*FB_KSZ)             // 36864
#define FB_P    (FB_V + 2*FB_KSZ)      // 73728 ; P = 128*136*2 = 34816 B
#define FB_MUL  (FB_P + 34816)         // 108544 ; 2*128 floats
#define FB_ADD  (FB_MUL + 1024)        // 109568
#define FA_SMEM (FB_ADD + 1024)        // 110592 B

#define LOG2E 1.4426950408889634f

__global__ __launch_bounds__(256, 1) void flash_kernel(
    const __half* __restrict__ QKV, const int* __restrict__ mask,
    __half* __restrict__ O)
{
    extern __shared__ char smc[];
    float* fmul = (float*)(smc + FB_MUL);
    float* fadd = (float*)(smc + FB_ADD);
    uint32_t sb = (uint32_t)__cvta_generic_to_shared(smc);

    const int tid = threadIdx.x, lane = tid & 31, w = tid >> 5;
    const int g = lane >> 2, tg = lane & 3, lq = lane & 7, lg = lane >> 3;
    const int bh = blockIdx.y, b = bh >> 4, h = bh & 15;
    const int hcol = h * DK_;
    const int qbase = blockIdx.x * 128;
    const long rowB = (long)b * S_;

    // ---- Q fragments (unscaled; scale*log2e folded into mask mult) ----
    uint32_t qa[4][4];
    {
        const __half* q0 = QKV + (rowB + qbase + w*16 + g)*(long)D3_ + hcol;
        const __half* q8 = q0 + 8*(long)D3_;
        #pragma unroll
        for (int ks=0; ks<4; ks++){
            qa[ks][0] = *(const uint32_t*)(q0 + ks*16 + 2*tg);
            qa[ks][1] = *(const uint32_t*)(q8 + ks*16 + 2*tg);
            qa[ks][2] = *(const uint32_t*)(q0 + ks*16 + 2*tg + 8);
            qa[ks][3] = *(const uint32_t*)(q8 + ks*16 + 2*tg + 8);
        }
    }

    // ---- prologue: mask buf0 + K0,V0 ----
    if (tid < 128){
        int mv = mask[rowB + tid];
        fmul[tid] = mv ? 0.125f*LOG2E : 0.f;
        fadd[tid] = mv ? 0.f : -1e9f*LOG2E;
    }
    {
        const __half* Kg = QKV + rowB*D3_ + D_   + hcol;
        const __half* Vg = QKV + rowB*D3_ + 2*D_ + hcol;
        #pragma unroll
        for (int i=0;i<4;i++){
            int idx = i*256 + tid, r = idx >> 3, c = idx & 7;
            cpa16(sb + FB_K + r*144 + c*16, Kg + (long)r*D3_ + c*8);
        }
        #pragma unroll
        for (int i=0;i<4;i++){
            int idx = i*256 + tid, r = idx >> 3, c = idx & 7;
            cpa16(sb + FB_V + r*144 + c*16, Vg + (long)r*D3_ + c*8);
        }
        cpcommit();
    }

    float o_acc[8][4];
    #pragma unroll
    for (int j=0;j<8;j++){ o_acc[j][0]=0.f;o_acc[j][1]=0.f;o_acc[j][2]=0.f;o_acc[j][3]=0.f; }
    float m0 = -__int_as_float(0x7f800000), m1 = m0;
    float l0 = 0.f, l1 = 0.f;

    const int NT = S_ / 128;   // 16
    for (int it = 0; it < NT; it++){
        const int mb = it & 1;
        cpwait0();
        __syncthreads();

        if (it+1 < NT){
            const int nb = (it+1) & 1;
            const __half* Kg = QKV + (rowB + (it+1)*128)*(long)D3_ + D_   + hcol;
            const __half* Vg = QKV + (rowB + (it+1)*128)*(long)D3_ + 2*D_ + hcol;
            #pragma unroll
            for (int i=0;i<4;i++){
                int idx = i*256 + tid, r = idx >> 3, c = idx & 7;
                cpa16(sb + FB_K + nb*FB_KSZ + r*144 + c*16, Kg + (long)r*D3_ + c*8);
            }
            #pragma unroll
            for (int i=0;i<4;i++){
                int idx = i*256 + tid, r = idx >> 3, c = idx & 7;
                cpa16(sb + FB_V + nb*FB_KSZ + r*144 + c*16, Vg + (long)r*D3_ + c*8);
            }
            cpcommit();
            if (tid < 128){
                int mv = mask[rowB + (it+1)*128 + tid];
                fmul[nb*128 + tid] = mv ? 0.125f*LOG2E : 0.f;
                fadd[nb*128 + tid] = mv ? 0.f : -1e9f*LOG2E;
            }
        }

        // ---- scores: S = Q K^T ----
        float c[16][4];
        #pragma unroll
        for (int j=0;j<16;j++){ c[j][0]=0.f;c[j][1]=0.f;c[j][2]=0.f;c[j][3]=0.f; }
        {
            uint32_t kb_base = sb + FB_K + mb*FB_KSZ;
            #pragma unroll
            for (int ks=0; ks<4; ks++){
                #pragma unroll
                for (int jp=0;jp<8;jp++){
                    uint32_t b4[4];
                    int row = jp*16 + (lg>>1)*8 + lq;
                    int col = ks*16 + (lg&1)*8;
                    ldsm4(b4, kb_base + (uint32_t)(row*72 + col)*2);
                    mma16(c[2*jp],   qa[ks], &b4[0]);
                    mma16(c[2*jp+1], qa[ks], &b4[2]);
                }
            }
        }

        // ---- scale+mask (log2 domain) + online softmax via exp2 ----
        const float* Mu = fmul + mb*128;
        const float* Ad = fadd + mb*128;
        float mx0 = -3.0e38f, mx1 = -3.0e38f;
        #pragma unroll
        for (int j=0;j<16;j++){
            int cc = j*8 + 2*tg;
            float mu0 = Mu[cc], mu1 = Mu[cc+1];
            float ad0 = Ad[cc], ad1 = Ad[cc+1];
            c[j][0] = fmaf(c[j][0], mu0, ad0);
            c[j][1] = fmaf(c[j][1], mu1, ad1);
            c[j][2] = fmaf(c[j][2], mu0, ad0);
            c[j][3] = fmaf(c[j][3], mu1, ad1);
            mx0 = fmaxf(mx0, fmaxf(c[j][0], c[j][1]));
            mx1 = fmaxf(mx1, fmaxf(c[j][2], c[j][3]));
        }
        mx0 = fmaxf(mx0, __shfl_xor_sync(0xffffffffu, mx0, 1));
        mx0 = fmaxf(mx0, __shfl_xor_sync(0xffffffffu, mx0, 2));
        mx1 = fmaxf(mx1, __shfl_xor_sync(0xffffffffu, mx1, 1));
        mx1 = fmaxf(mx1, __shfl_xor_sync(0xffffffffu, mx1, 2));

        float nm0 = fmaxf(m0, mx0), nm1 = fmaxf(m1, mx1);
        float cr0 = exp2f(m0 - nm0), cr1 = exp2f(m1 - nm1);
        float s0 = 0.f, s1 = 0.f;
        #pragma unroll
        for (int j=0;j<16;j++){
            c[j][0] = exp2f(c[j][0] - nm0);
            c[j][1] = exp2f(c[j][1] - nm0);
            c[j][2] = exp2f(c[j][2] - nm1);
            c[j][3] = exp2f(c[j][3] - nm1);
            s0 += c[j][0] + c[j][1];
            s1 += c[j][2] + c[j][3];
        }
        s0 += __shfl_xor_sync(0xffffffffu, s0, 1);
        s0 += __shfl_xor_sync(0xffffffffu, s0, 2);
        s1 += __shfl_xor_sync(0xffffffffu, s1, 1);
        s1 += __shfl_xor_sync(0xffffffffu, s1, 2);
        l0 = l0*cr0 + s0;  l1 = l1*cr1 + s1;
        m0 = nm0;          m1 = nm1;
        #pragma unroll
        for (int j=0;j<8;j++){
            o_acc[j][0]*=cr0; o_acc[j][1]*=cr0; o_acc[j][2]*=cr1; o_acc[j][3]*=cr1;
        }

        // ---- P (fp16) to smem, warp-private rows ----
        {
            char* Pr0 = smc + FB_P + ((w*16+g)*136 + 2*tg)*2;
            char* Pr8 = Pr0 + 8*136*2;
            #pragma unroll
            for (int j=0;j<16;j++){
                *(__half2*)(Pr0 + j*16) = __floats2half2_rn(c[j][0], c[j][1]);
                *(__half2*)(Pr8 + j*16) = __floats2half2_rn(c[j][2], c[j][3]);
            }
        }
        __syncwarp();

        // ---- O += P @ V ----
        {
            uint32_t p_base = sb + FB_P;
            uint32_t v_base = sb + FB_V + mb*FB_KSZ;
            #pragma unroll
            for (int kbi=0; kbi<8; kbi++){
                uint32_t a4[4];
                {
                    int row = w*16 + (lg&1)*8 + lq;
                    int col = kbi*16 + (lg>>1)*8;
                    ldsm4(a4, p_base + (uint32_t)(row*136 + col)*2);
                }
                #pragma unroll
                for (int jo=0; jo<8; jo+=2){
                    uint32_t b4[4];
                    int row = kbi*16 + (lg&1)*8 + lq;       // kv
                    int col = (jo + (lg>>1))*8;             // dk
                    ldsm4t(b4, v_base + (uint32_t)(row*72 + col)*2);
                    mma16(o_acc[jo],   a4, &b4[0]);
                    mma16(o_acc[jo+1], a4, &b4[2]);
                }
            }
        }
    }

    // ---- epilogue: O / l, fp16 output ----
    float inv0 = 1.f / l0, inv1 = 1.f / l1;
    __half* o0 = O + (rowB + qbase + w*16 + g)*(long)D_ + hcol + 2*tg;
    __half* o8 = o0 + 8*(long)D_;
    #pragma unroll
    for (int jo=0; jo<8; jo++){
        *(__half2*)(o0 + jo*8) = __floats2half2_rn(o_acc[jo][0]*inv0, o_acc[jo][1]*inv0);
        *(__half2*)(o8 + jo*8) = __floats2half2_rn(o_acc[jo][2]*inv1, o_acc[jo][3]*inv1);
    }
}

// ---------------------------------------------------------------------------
// Launch
// ---------------------------------------------------------------------------
extern "C" void kernel_launch(void* const* d_in, const int* in_sizes, int n_in,
                              void* d_out, int out_size)
{
    const float* x    = (const float*)d_in[0];
    const int*   mask = (const int*)  d_in[1];
    const float* wq = (const float*)d_in[2];  const float* bq = (const float*)d_in[3];
    const float* wk = (const float*)d_in[4];  const float* bk = (const float*)d_in[5];
    const float* wv = (const float*)d_in[6];  const float* bv = (const float*)d_in[7];
    const float* wo = (const float*)d_in[8];  const float* bo = (const float*)d_in[9];
    const float* w1 = (const float*)d_in[10]; const float* b1 = (const float*)d_in[11];
    const float* w2 = (const float*)d_in[12]; const float* b2 = (const float*)d_in[13];
    const float* a1 = (const float*)d_in[14]; const float* c1 = (const float*)d_in[15];
    const float* a2 = (const float*)d_in[16]; const float* c2 = (const float*)d_in[17];
    float* out = (float*)d_out;

    void* p;
    __half *xnh,*qkvh,*aoh,*hnh,*f1h,*wqkvh,*woh,*w1h,*w2h;
    float *hb,*bqkvb;
    cudaGetSymbolAddress(&p, g_xnh);   xnh   = (__half*)p;
    cudaGetSymbolAddress(&p, g_qkvh);  qkvh  = (__half*)p;
    cudaGetSymbolAddress(&p, g_aoh);   aoh   = (__half*)p;
    cudaGetSymbolAddress(&p, g_hnh);   hnh   = (__half*)p;
    cudaGetSymbolAddress(&p, g_f1h);   f1h   = (__half*)p;
    cudaGetSymbolAddress(&p, g_wqkvh); wqkvh = (__half*)p;
    cudaGetSymbolAddress(&p, g_woh);   woh   = (__half*)p;
    cudaGetSymbolAddress(&p, g_w1h);   w1h   = (__half*)p;
    cudaGetSymbolAddress(&p, g_w2h);   w2h   = (__half*)p;
    cudaGetSymbolAddress(&p, g_h);     hb    = (float*)p;
    cudaGetSymbolAddress(&p, g_bqkv);  bqkvb = (float*)p;

    constexpr int SMEM_G = 3*(128+128)*72*2;   // 110592 B per CTA (x2/SM)
    cudaFuncSetAttribute((const void*)gemm_h<true,false,false,true >,
                         cudaFuncAttributeMaxDynamicSharedMemorySize, SMEM_G);
    cudaFuncSetAttribute((const void*)gemm_h<true,false,true ,false>,
                         cudaFuncAttributeMaxDynamicSharedMemorySize, SMEM_G);
    cudaFuncSetAttribute((const void*)gemm_h<true,true ,false,true >,
                         cudaFuncAttributeMaxDynamicSharedMemorySize, SMEM_G);
    cudaFuncSetAttribute((const void*)flash_kernel,
                         cudaFuncAttributeMaxDynamicSharedMemorySize, FA_SMEM);

    // 0) all weight conversions in one launch + bias concat
    f2h_all<<<1536, 256>>>(wq, wk, wv, wo, w1, w2, wqkvh, woh, w1h, w2h);
    bcat_kernel<<<D3_/256,256>>>(bq, bk, bv, bqkvb);

    // 1) LN1 -> fp16
    ln_kernel<<<M_, 256>>>(x, a1, c1, xnh);

    // 2) fused QKV projection [8192,1024] @ [3072,1024]^T -> fp16
    gemm_h<true,false,false,true><<<dim3(D3_/128, M_/128), 256, SMEM_G>>>(
        xnh, D_, wqkvh, D_, qkvh, D3_, bqkvb, nullptr, D_);

    // 3) fused flash attention -> fp16 ao
    flash_kernel<<<dim3(S_/128, B_*H_), 256, FA_SMEM>>>(qkvh, mask, aoh);

    // 4) O projection + residual x -> fp32 h
    gemm_h<true,false,true,false><<<dim3(D_/128, M_/128), 256, SMEM_G>>>(
        aoh, D_, woh, D_, hb, D_, bo, x, D_);

    // 5) LN2 -> fp16
    ln_kernel<<<M_, 256>>>(hb, a2, c2, hnh);

    // 6) FFN1 + ReLU -> fp16
    gemm_h<true,true,false,true><<<dim3(DFF_/128, M_/128), 256, SMEM_G>>>(
        hnh, D_, w1h, D_, f1h, DFF_, b1, nullptr, D_);

    // 7) FFN2 + residual h -> fp32 out
    gemm_h<true,false,true,false><<<dim3(D_/128, M_/128), 256, SMEM_G>>>(
        f1h, DFF_, w2h, DFF_, out, D_, b2, hb, DFF_);
}